// round 13
// baseline (speedup 1.0000x reference)
#include <cuda_runtime.h>
#include <cuda_bf16.h>
#include <stdint.h>

#define Bn 2
#define Sn 512
#define Hn 768
#define En 64
#define Mn 64
#define Rn 128
#define SIZE_E 32
#define CLS_ID 101
#define REP_K (2*Hn + SIZE_E)    /* 1568 */
#define REL_K (3*Hn + 2*SIZE_E)  /* 2368 */
#define NEGV (-1e30f)

// activation bf16 plane offsets (elements)
#define A_REP0  0
#define A_REP1  200704
#define A_REPR0 401408
#define A_REPR1 1007616
#define A_H1_0  1613824
#define A_H1_1  1810432
#define A_PLANE 2007040

// ------------------------- device scratch -------------------------
__device__ float d_ctx[Bn*Hn];
__device__ float d_ppool[768*4*Hn];
__device__ int   d_pany[768*4];
__device__ __nv_bfloat16 d_a_hi[A_PLANE];
__device__ __nv_bfloat16 d_a_lo[A_PLANE];
__device__ float d_cpart[2359296];
__device__ float d_hid_ner[128*Hn];
__device__ float d_hid_emd[128*Hn];
__device__ float d_h2_rel[256*Hn];
__device__ float d_h2_cr [256*Hn];

#define S0_ELEM (128*Hn)       /* 98304 */
#define S1_BASE 786432
#define S1_ELEM (256*Hn)       /* 196608 */

// ------------------------- helpers -------------------------
__device__ __forceinline__ uint32_t smem_u32(const void* p) {
    uint32_t r;
    asm("{ .reg .u64 t; cvta.to.shared.u64 t, %1; cvt.u32.u64 %0, t; }" : "=r"(r) : "l"(p));
    return r;
}
__device__ __forceinline__ void ldsm4(uint32_t addr, uint32_t& r0, uint32_t& r1,
                                      uint32_t& r2, uint32_t& r3) {
    asm volatile("ldmatrix.sync.aligned.m8n8.x4.shared.b16 {%0,%1,%2,%3}, [%4];"
                 : "=r"(r0), "=r"(r1), "=r"(r2), "=r"(r3) : "r"(addr));
}
__device__ __forceinline__ void mma16816(float* d, const uint32_t* a, uint32_t b0, uint32_t b1) {
    asm volatile("mma.sync.aligned.m16n8k16.row.col.f32.bf16.bf16.f32 "
        "{%0,%1,%2,%3}, {%4,%5,%6,%7}, {%8,%9}, {%0,%1,%2,%3};"
        : "+f"(d[0]), "+f"(d[1]), "+f"(d[2]), "+f"(d[3])
        : "r"(a[0]), "r"(a[1]), "r"(a[2]), "r"(a[3]), "r"(b0), "r"(b1));
}
__device__ __forceinline__ void cvt_hilo(float4 v, uint2& h, uint2& l)
{
    __nv_bfloat162 hx = __floats2bfloat162_rn(v.x, v.y);
    __nv_bfloat162 hz = __floats2bfloat162_rn(v.z, v.w);
    float2 fx = __bfloat1622float2(hx);
    float2 fz = __bfloat1622float2(hz);
    __nv_bfloat162 lx = __floats2bfloat162_rn(v.x - fx.x, v.y - fx.y);
    __nv_bfloat162 lz = __floats2bfloat162_rn(v.z - fz.x, v.w - fz.y);
    h.x = *(uint32_t*)&hx; h.y = *(uint32_t*)&hz;
    l.x = *(uint32_t*)&lx; l.y = *(uint32_t*)&lz;
}
__device__ __forceinline__ void cvt_store(uint32_t phi, uint32_t plo, float4 v)
{
    uint2 h, l; cvt_hilo(v, h, l);
    asm volatile("st.shared.v2.b32 [%0], {%1, %2};" :: "r"(phi), "r"(h.x), "r"(h.y) : "memory");
    asm volatile("st.shared.v2.b32 [%0], {%1, %2};" :: "r"(plo), "r"(l.x), "r"(l.y) : "memory");
}
__device__ __forceinline__ float4 pool_max4(int span, int cc)
{
    float4 v = *(const float4*)&d_ppool[((size_t)span*4 + 0)*Hn + cc];
    #pragma unroll
    for (int ch = 1; ch < 4; ch++) {
        float4 p = *(const float4*)&d_ppool[((size_t)span*4 + ch)*Hn + cc];
        v.x = fmaxf(v.x, p.x); v.y = fmaxf(v.y, p.y);
        v.z = fmaxf(v.z, p.z); v.w = fmaxf(v.w, p.w);
    }
    return v;
}

// ------------------------- pooled masked max (+ ctx blocks at end) -------------------------
__global__ __launch_bounds__(192) void pool_kernel(
    const int* __restrict__ em, const int* __restrict__ mm,
    const int* __restrict__ rm, const int* __restrict__ fm,
    const int* __restrict__ input_ids,
    const float* __restrict__ emb)
{
    int blk = blockIdx.x;
    int tid = threadIdx.x;
    if (blk >= 192) {
        int b = blk - 192;
        __shared__ int cidx;
        if (tid == 0) cidx = Sn;
        __syncthreads();
        for (int s = tid; s < Sn; s += blockDim.x)
            if (input_ids[b*Sn + s] == CLS_ID) atomicMin(&cidx, s);
        __syncthreads();
        int ci = (cidx == Sn) ? 0 : cidx;
        for (int h = tid; h < Hn; h += blockDim.x)
            d_ctx[b*Hn + h] = emb[((size_t)b*Sn + ci)*Hn + h];
        return;
    }
    const int* masks; int Kspans, sgbase, local;
    if (blk < 32)       { masks = em; Kspans = En; sgbase = 0;   local = blk; }
    else if (blk < 64)  { masks = mm; Kspans = Mn; sgbase = 128; local = blk - 32; }
    else if (blk < 128) { masks = rm; Kspans = Rn; sgbase = 256; local = blk - 64; }
    else                { masks = fm; Kspans = Rn; sgbase = 512; local = blk - 128; }

    int gpb   = Kspans >> 4;
    int b     = local / (gpb*4);
    int rem   = local % (gpb*4);
    int g     = rem >> 2;
    int chunk = rem & 3;
    int s0    = chunk * 128;
    int k0    = g * 16;
    int sg0   = sgbase + b*Kspans + k0;

    __shared__ unsigned mw[128];
    __shared__ unsigned anyw;
    if (tid < 128) mw[tid] = 0u;
    if (tid == 0) anyw = 0u;
    __syncthreads();

    for (int i = tid; i < 16*128; i += 192) {
        int t = i >> 7, sl = i & 127;
        if (masks[(size_t)(b*Kspans + k0 + t)*Sn + s0 + sl] != 0)
            atomicOr(&mw[sl], 1u << t);
    }
    __syncthreads();

    unsigned aw = 0u;
    for (int sl = tid; sl < 128; sl += 192) aw |= mw[sl];
    if (aw) atomicOr(&anyw, aw);
    __syncthreads();

    int h0 = tid * 4;
    float4 acc[16];
    #pragma unroll
    for (int t = 0; t < 16; t++) acc[t] = make_float4(NEGV, NEGV, NEGV, NEGV);

    const float* ebase = emb + ((size_t)b*Sn + s0)*Hn + h0;
    for (int sl = 0; sl < 128; sl++) {
        float4 v = *(const float4*)(ebase + (size_t)sl*Hn);
        unsigned m = mw[sl];
        #pragma unroll
        for (int t = 0; t < 16; t++) {
            if (m & (1u << t)) {
                acc[t].x = fmaxf(acc[t].x, v.x);
                acc[t].y = fmaxf(acc[t].y, v.y);
                acc[t].z = fmaxf(acc[t].z, v.z);
                acc[t].w = fmaxf(acc[t].w, v.w);
            }
        }
    }
    unsigned a = anyw;
    #pragma unroll
    for (int t = 0; t < 16; t++)
        *(float4*)&d_ppool[((size_t)(sg0 + t)*4 + chunk)*Hn + h0] = acc[t];
    if (tid < 16) d_pany[(sg0 + tid)*4 + chunk] = (a >> tid) & 1u;
}

// ------------------------- assemble (combine fused): write bf16 hi/lo planes ----------------
__global__ void assemble_kernel(
    const int* __restrict__ entity_sizes, const int* __restrict__ mention_sizes,
    const int* __restrict__ relations,    const int* __restrict__ references,
    const float* __restrict__ ner_size_emb, const float* __restrict__ emd_size_emb)
{
    int row = blockIdx.x;
    int tid = threadIdx.x;
    if (row < 256) {
        int prob = row >> 7;
        int r = row & 127;
        int b = r >> 6;
        int span = prob*128 + r;
        int sz = (prob ? mention_sizes : entity_sizes)[r];
        const float* se = (prob ? emd_size_emb : ner_size_emb) + (size_t)sz*SIZE_E;
        size_t off = (prob ? A_REP1 : A_REP0) + (size_t)r*REP_K;
        for (int i = tid; i < REP_K/4; i += 256) {
            int c = i * 4; float4 v;
            if (c < Hn)            v = *(const float4*)(d_ctx + b*Hn + c);
            else if (c < 2*Hn)     v = pool_max4(span, c - Hn);
            else                   v = *(const float4*)(se + c - 2*Hn);
            uint2 h, l; cvt_hilo(v, h, l);
            *(uint2*)&d_a_hi[off + c] = h;
            *(uint2*)&d_a_lo[off + c] = l;
        }
    } else {
        int isrel = (row < 512);
        int r = isrel ? row - 256 : row - 512;
        int b = r >> 7;
        int span_ctx = (isrel ? 256 : 512) + r;
        const int*   idxs  = isrel ? relations : references;
        const int*   szs   = isrel ? entity_sizes : mention_sizes;
        const float* semb  = isrel ? ner_size_emb : emd_size_emb;
        int pbase = isrel ? 0 : 128;
        int e1 = idxs[r*2], e2 = idxs[r*2 + 1];
        int span1 = pbase + b*64 + e1, span2 = pbase + b*64 + e2;
        const float* s1 = semb + (size_t)szs[b*64 + e1]*SIZE_E;
        const float* s2 = semb + (size_t)szs[b*64 + e2]*SIZE_E;
        int any = d_pany[span_ctx*4] | d_pany[span_ctx*4+1]
                | d_pany[span_ctx*4+2] | d_pany[span_ctx*4+3];
        size_t off = (isrel ? A_REPR0 : A_REPR1) + (size_t)r*REL_K;
        for (int i = tid; i < REL_K/4; i += 256) {
            int c = i * 4; float4 v;
            if (c < Hn) {
                v = pool_max4(span_ctx, c);
                if (!any) v = make_float4(0.f, 0.f, 0.f, 0.f);
            }
            else if (c < 2*Hn)            v = pool_max4(span1, c - Hn);
            else if (c < 3*Hn)            v = pool_max4(span2, c - 2*Hn);
            else if (c < 3*Hn + SIZE_E)   v = *(const float4*)(s1 + c - 3*Hn);
            else                          v = *(const float4*)(s2 + c - 3*Hn - SIZE_E);
            uint2 h, l; cvt_hilo(v, h, l);
            *(uint2*)&d_a_hi[off + c] = h;
            *(uint2*)&d_a_lo[off + c] = l;
        }
    }
}

// ------------------------- HMMA GEMM: cp.async A planes + W reg-prefetch -------------------
#define PADK 72
#define OFF_AHI 0
#define OFF_ALO (128*PADK*2)
#define OFF_BHI (2*128*PADK*2)
#define OFF_BLO (OFF_BHI + 64*PADK*2)
#define BUFSZ   (OFF_BLO + 64*PADK*2)   /* 55296 */

struct Frag {
    uint32_t ah[2][4], al[2][4], bh[2][4], bl[2][4];
};

__device__ __forceinline__ void load_frag(Frag& f, uint32_t base, int k0,
                                          int wm, int wn, int rA, int cAo, int rB, int cBo)
{
    #pragma unroll
    for (int mi = 0; mi < 2; mi++) {
        uint32_t oa = (uint32_t)((wm*32 + mi*16 + rA) * PADK + k0 + cAo) * 2;
        ldsm4(base + OFF_AHI + oa, f.ah[mi][0], f.ah[mi][1], f.ah[mi][2], f.ah[mi][3]);
        ldsm4(base + OFF_ALO + oa, f.al[mi][0], f.al[mi][1], f.al[mi][2], f.al[mi][3]);
    }
    #pragma unroll
    for (int bi = 0; bi < 2; bi++) {
        uint32_t ob = (uint32_t)((wn*32 + bi*16 + rB) * PADK + k0 + cBo) * 2;
        ldsm4(base + OFF_BHI + ob, f.bh[bi][0], f.bh[bi][1], f.bh[bi][2], f.bh[bi][3]);
        ldsm4(base + OFF_BLO + ob, f.bl[bi][0], f.bl[bi][1], f.bl[bi][2], f.bl[bi][3]);
    }
}

// three full sweeps: successive HMMAs on the same accumulator are separated by
// 7 independent HMMAs, hiding the HMMA RAW latency within one warp's stream.
// Per-accumulator summation order (hh -> hl -> lh) is unchanged => bit-identical.
__device__ __forceinline__ void do_mma(float acc[2][4][4], const Frag& f)
{
    #pragma unroll
    for (int mi = 0; mi < 2; mi++)
        #pragma unroll
        for (int ni = 0; ni < 4; ni++) {
            int bi = ni >> 1, p = (ni & 1) * 2;
            mma16816(acc[mi][ni], f.ah[mi], f.bh[bi][p], f.bh[bi][p+1]);
        }
    #pragma unroll
    for (int mi = 0; mi < 2; mi++)
        #pragma unroll
        for (int ni = 0; ni < 4; ni++) {
            int bi = ni >> 1, p = (ni & 1) * 2;
            mma16816(acc[mi][ni], f.ah[mi], f.bl[bi][p], f.bl[bi][p+1]);
        }
    #pragma unroll
    for (int mi = 0; mi < 2; mi++)
        #pragma unroll
        for (int ni = 0; ni < 4; ni++) {
            int bi = ni >> 1, p = (ni & 1) * 2;
            mma16816(acc[mi][ni], f.al[mi], f.bh[bi][p], f.bh[bi][p+1]);
        }
}

__device__ __forceinline__ void cp_async_A(
    uint32_t base, const __nv_bfloat16* Ah, const __nv_bfloat16* Al,
    int K, int m0, int kb, int tid)
{
    #pragma unroll
    for (int i = 0; i < 4; i++) {
        int u = tid + (i << 8);
        int arow = u >> 3, c16 = u & 7;
        uint32_t o = (uint32_t)arow * (PADK*2) + c16*16;
        const __nv_bfloat16* ph = Ah + (size_t)(m0 + arow)*K + kb + c16*8;
        const __nv_bfloat16* pl = Al + (size_t)(m0 + arow)*K + kb + c16*8;
        asm volatile("cp.async.ca.shared.global [%0], [%1], 16;"
                     :: "r"(base + OFF_AHI + o), "l"(ph) : "memory");
        asm volatile("cp.async.ca.shared.global [%0], [%1], 16;"
                     :: "r"(base + OFF_ALO + o), "l"(pl) : "memory");
    }
    asm volatile("cp.async.commit_group;" ::: "memory");
}

__device__ __forceinline__ void ldg_W(float4 (&wbuf)[4], const float* W,
                                      int K, int n0, int kb, int wrow, int c4)
{
    int kc = K - kb; if (kc > 64) kc = 64;
    #pragma unroll
    for (int i = 0; i < 4; i++)
        if (c4 < kc)
            wbuf[i] = *(const float4*)(W + (size_t)(n0 + wrow + i*16)*K + kb + c4);
}

__global__ __launch_bounds__(256, 2) void gemm_mma_kernel(
    const float* __restrict__ Wa, const float* __restrict__ Wb,
    const float* __restrict__ Wc, const float* __restrict__ Wd,
    const float* __restrict__ ba, const float* __restrict__ bb,
    int mode)
{
    extern __shared__ char smem[];
    uint32_t sb = smem_u32(smem);
    int tid = threadIdx.x;
    int wid = tid >> 5, lane = tid & 31;
    int wm = wid & 3, wn = wid >> 2;

    // resolve job
    const __nv_bfloat16 *Ah, *Al; const float* W; float* Out;
    const float* biasp = nullptr;
    int K, m0, n0, c0, c1;
    int bx = blockIdx.x;
    if (mode == 0 && bx < 96) {
        int prob = bx / 48, r = bx % 48, nt = r >> 2, sp = r & 3;
        size_t aoff = prob ? A_REP1 : A_REP0;
        Ah = d_a_hi + aoff; Al = d_a_lo + aoff;
        W = prob ? Wb : Wa;
        Out = d_cpart + (size_t)(prob*4 + sp) * S0_ELEM;
        K = REP_K; m0 = 0; n0 = nt * 64;
        int nc = (K + 63) >> 6;
        c0 = sp * nc / 4; c1 = (sp + 1) * nc / 4;
    } else if (mode == 0) {
        int i = bx - 96;
        int prob = i / 96, r = i % 96;
        int mt = r / 48, r2 = r % 48, nt = r2 >> 2, sp = r2 & 3;
        size_t aoff = prob ? A_REPR1 : A_REPR0;
        Ah = d_a_hi + aoff; Al = d_a_lo + aoff;
        W = prob ? Wd : Wc; K = REL_K;
        Out = d_cpart + S1_BASE + (size_t)(prob*4 + sp) * S1_ELEM;
        m0 = mt * 128; n0 = nt * 64;
        int nc = (K + 63) >> 6;
        c0 = sp * nc / 4; c1 = (sp + 1) * nc / 4;
    } else {
        // stage2: NO split-K; 2 probs x 2 m-tiles x 12 n-tiles = 48 CTAs; bias+relu fused
        int i = bx;
        int prob = i / 24, r = i % 24;
        int mt = r / 12, nt = r % 12;
        size_t aoff = prob ? A_H1_1 : A_H1_0;
        Ah = d_a_hi + aoff; Al = d_a_lo + aoff;
        W = prob ? Wb : Wa; K = Hn;
        Out = prob ? d_h2_cr : d_h2_rel;
        biasp = prob ? bb : ba;
        m0 = mt * 128; n0 = nt * 64;
        c0 = 0; c1 = 12;
    }

    int wrow_ld = tid >> 4, wc4_ld = (tid & 15) << 2;

    float acc[2][4][4];
    #pragma unroll
    for (int mi = 0; mi < 2; mi++)
        #pragma unroll
        for (int ni = 0; ni < 4; ni++)
            #pragma unroll
            for (int q = 0; q < 4; q++) acc[mi][ni][q] = 0.f;

    int g = lane >> 3;
    int rA = (lane & 7) + ((g & 1) << 3);
    int cAo = (g & 2) << 2;
    int rB = (lane & 7) + ((g & 2) << 2);
    int cBo = (g & 1) << 3;

    Frag f0;
    float4 wbuf[4];

    // prologue: W(c0) into registers; cp.async A(c0)
    ldg_W(wbuf, W, K, n0, c0 << 6, wrow_ld, wc4_ld);
    cp_async_A(sb + (uint32_t)(c0 & 1) * BUFSZ, Ah, Al, K, m0, c0 << 6, tid);

    for (int c = c0; c < c1; c++) {
        uint32_t base = sb + (uint32_t)(c & 1) * BUFSZ;

        // store W(c) from registers (cvt inline)
        {
            uint32_t o = (uint32_t)(wrow_ld * PADK + wc4_ld) * 2;
            #pragma unroll
            for (int i = 0; i < 4; i++)
                cvt_store(base + OFF_BHI + o + i*16*PADK*2,
                          base + OFF_BLO + o + i*16*PADK*2, wbuf[i]);
        }

        asm volatile("cp.async.wait_group 0;" ::: "memory");
        __syncthreads();   // A(c) + W(c) visible; all warps done with MMA(c-1)

        // issue next chunk's loads (covered by MMA below)
        if (c + 1 < c1) {
            cp_async_A(sb + (uint32_t)((c + 1) & 1) * BUFSZ, Ah, Al, K, m0, (c + 1) << 6, tid);
            ldg_W(wbuf, W, K, n0, (c + 1) << 6, wrow_ld, wc4_ld);
        }

        int kc = K - (c << 6); if (kc > 64) kc = 64;
        int steps = kc >> 4;
        #pragma unroll 4
        for (int s = 0; s < steps; s++) {
            load_frag(f0, base, s << 4, wm, wn, rA, cAo, rB, cBo);
            do_mma(acc, f0);
        }
    }

    // epilogue
    int r0 = lane >> 2, cq = (lane & 3) * 2;
    if (biasp) {
        // stage2: bias + relu fused, write h2 directly
        #pragma unroll
        for (int mi = 0; mi < 2; mi++) {
            #pragma unroll
            for (int ni = 0; ni < 4; ni++) {
                int col = n0 + wn*32 + ni*8 + cq;
                float b0v = biasp[col], b1v = biasp[col + 1];
                int row = m0 + wm*32 + mi*16 + r0;
                float2 v0, v1;
                v0.x = fmaxf(acc[mi][ni][0] + b0v, 0.f);
                v0.y = fmaxf(acc[mi][ni][1] + b1v, 0.f);
                v1.x = fmaxf(acc[mi][ni][2] + b0v, 0.f);
                v1.y = fmaxf(acc[mi][ni][3] + b1v, 0.f);
                *(float2*)(Out + (size_t)row * Hn + col) = v0;
                *(float2*)(Out + (size_t)(row + 8) * Hn + col) = v1;
            }
        }
    } else {
        #pragma unroll
        for (int mi = 0; mi < 2; mi++) {
            #pragma unroll
            for (int ni = 0; ni < 4; ni++) {
                int col = n0 + wn*32 + ni*8 + cq;
                int row = m0 + wm*32 + mi*16 + r0;
                float2 v0 = make_float2(acc[mi][ni][0], acc[mi][ni][1]);
                float2 v1 = make_float2(acc[mi][ni][2], acc[mi][ni][3]);
                *(float2*)(Out + (size_t)row * Hn + col) = v0;
                *(float2*)(Out + (size_t)(row + 8) * Hn + col) = v1;
            }
        }
    }
}

// ------------------------- finalize A: stage0 (fp32 hid) + stage1 (bf16 h1 planes) ----------
__global__ void finalizeA_kernel(
    const float* __restrict__ b_ner, const float* __restrict__ b_emd,
    const float* __restrict__ b_rel, const float* __restrict__ b_cr)
{
    int prob = blockIdx.y;
    int idx4 = (blockIdx.x * 256 + threadIdx.x) * 4;
    if (idx4 < S0_ELEM) {
        const float* p = d_cpart + (size_t)(prob*4) * S0_ELEM + idx4;
        float4 a = *(const float4*)p;
        float4 b = *(const float4*)(p + S0_ELEM);
        float4 c = *(const float4*)(p + 2*(size_t)S0_ELEM);
        float4 d = *(const float4*)(p + 3*(size_t)S0_ELEM);
        float4 bb = *(const float4*)((prob ? b_emd : b_ner) + (idx4 % Hn));
        float4 r;
        r.x = fmaxf((a.x + b.x) + (c.x + d.x) + bb.x, 0.f);
        r.y = fmaxf((a.y + b.y) + (c.y + d.y) + bb.y, 0.f);
        r.z = fmaxf((a.z + b.z) + (c.z + d.z) + bb.z, 0.f);
        r.w = fmaxf((a.w + b.w) + (c.w + d.w) + bb.w, 0.f);
        *(float4*)((prob ? d_hid_emd : d_hid_ner) + idx4) = r;
    } else {
        int j = idx4 - S0_ELEM;
        if (j >= S1_ELEM) return;
        const float* p = d_cpart + S1_BASE + (size_t)(prob*4) * S1_ELEM + j;
        float4 a = *(const float4*)p;
        float4 b = *(const float4*)(p + S1_ELEM);
        float4 c = *(const float4*)(p + 2*(size_t)S1_ELEM);
        float4 d = *(const float4*)(p + 3*(size_t)S1_ELEM);
        float4 bb = *(const float4*)((prob ? b_cr : b_rel) + (j % Hn));
        float4 r;
        r.x = fmaxf((a.x + b.x) + (c.x + d.x) + bb.x, 0.f);
        r.y = fmaxf((a.y + b.y) + (c.y + d.y) + bb.y, 0.f);
        r.z = fmaxf((a.z + b.z) + (c.z + d.z) + bb.z, 0.f);
        r.w = fmaxf((a.w + b.w) + (c.w + d.w) + bb.w, 0.f);
        uint2 h, l; cvt_hilo(r, h, l);
        size_t off = (prob ? A_H1_1 : A_H1_0) + j;
        *(uint2*)&d_a_hi[off] = h;
        *(uint2*)&d_a_lo[off] = l;
    }
}

// ------------------------- heads -------------------------
__global__ void heads_kernel(
    const float* __restrict__ ner_hw, const float* __restrict__ ner_hb,
    const float* __restrict__ emd_hw, const float* __restrict__ emd_hb,
    const float* __restrict__ rel_w3, const float* __restrict__ rel_b3,
    const float* __restrict__ cr_w3,  const float* __restrict__ cr_b3,
    float* __restrict__ out)
{
    int gwarp = (blockIdx.x * blockDim.x + threadIdx.x) >> 5;
    int lane = threadIdx.x & 31;
    if (gwarp >= 3840) return;
    const float* A; const float* Wr; float bias;
    if (gwarp < 1280) {
        int r = gwarp / 10, n = gwarp % 10;
        A = d_hid_ner + (size_t)r*Hn; Wr = ner_hw + (size_t)n*Hn; bias = ner_hb[n];
    } else if (gwarp < 3328) {
        int i = gwarp - 1280; int r = i / 8, n = i % 8;
        A = d_h2_rel + (size_t)r*Hn; Wr = rel_w3 + (size_t)n*Hn; bias = rel_b3[n];
    } else if (gwarp < 3584) {
        int i = gwarp - 3328; int r = i / 2, n = i & 1;
        A = d_hid_emd + (size_t)r*Hn; Wr = emd_hw + (size_t)n*Hn; bias = emd_hb[n];
    } else {
        int i = gwarp - 3584;
        A = d_h2_cr + (size_t)i*Hn; Wr = cr_w3; bias = cr_b3[0];
    }
    float s = 0.f;
    for (int k = lane*4; k < Hn; k += 128) {
        float4 a = *(const float4*)(A + k);
        float4 w = *(const float4*)(Wr + k);
        s += a.x*w.x + a.y*w.y + a.z*w.z + a.w*w.w;
    }
    #pragma unroll
    for (int o = 16; o; o >>= 1) s += __shfl_xor_sync(0xffffffffu, s, o);
    if (lane == 0) out[gwarp] = s + bias;
}

// ------------------------- launch -------------------------
extern "C" void kernel_launch(void* const* d_in, const int* in_sizes, int n_in,
                              void* d_out, int out_size)
{
    const int*   input_ids       = (const int*)  d_in[0];
    const int*   entity_masks    = (const int*)  d_in[1];
    const int*   entity_sizes    = (const int*)  d_in[2];
    const int*   mention_masks   = (const int*)  d_in[3];
    const int*   mention_sizes   = (const int*)  d_in[4];
    const int*   relations       = (const int*)  d_in[5];
    const int*   rel_masks       = (const int*)  d_in[6];
    const int*   references      = (const int*)  d_in[7];
    const int*   references_masks= (const int*)  d_in[8];
    const float* emb             = (const float*)d_in[9];
    const float* ner_size_emb    = (const float*)d_in[10];
    const float* emd_size_emb    = (const float*)d_in[11];
    const float* ner_rep_w = (const float*)d_in[12]; const float* ner_rep_b = (const float*)d_in[13];
    const float* ner_head_w= (const float*)d_in[14]; const float* ner_head_b= (const float*)d_in[15];
    const float* emd_rep_w = (const float*)d_in[16]; const float* emd_rep_b = (const float*)d_in[17];
    const float* emd_head_w= (const float*)d_in[18]; const float* emd_head_b= (const float*)d_in[19];
    const float* rel_w1 = (const float*)d_in[20]; const float* rel_b1 = (const float*)d_in[21];
    const float* rel_w2 = (const float*)d_in[22]; const float* rel_b2 = (const float*)d_in[23];
    const float* rel_w3 = (const float*)d_in[24]; const float* rel_b3 = (const float*)d_in[25];
    const float* cr_w1  = (const float*)d_in[26]; const float* cr_b1  = (const float*)d_in[27];
    const float* cr_w2  = (const float*)d_in[28]; const float* cr_b2  = (const float*)d_in[29];
    const float* cr_w3  = (const float*)d_in[30]; const float* cr_b3  = (const float*)d_in[31];
    float* out = (float*)d_out;

    const int smem_bytes = 2 * BUFSZ;   // 110592/CTA; 2 CTA/SM
    cudaFuncSetAttribute(gemm_mma_kernel, cudaFuncAttributeMaxDynamicSharedMemorySize, smem_bytes);

    pool_kernel<<<194, 192>>>(entity_masks, mention_masks, rel_masks, references_masks,
                              input_ids, emb);
    assemble_kernel<<<768, 256>>>(entity_sizes, mention_sizes, relations, references,
                                  ner_size_emb, emd_size_emb);

    // launch 1: stage0 split-K4 (96) + stage1 split-K4 (192) = 288 CTAs
    gemm_mma_kernel<<<288, 256, smem_bytes>>>(ner_rep_w, emd_rep_w, rel_w1, cr_w1,
                                              nullptr, nullptr, 0);
    {
        dim3 f((S0_ELEM + S1_ELEM)/1024, 2);
        finalizeA_kernel<<<f, 256>>>(ner_rep_b, emd_rep_b, rel_b1, cr_b1);
    }

    // launch 2: stage2 no split-K (48 CTAs), bias+relu fused in epilogue
    gemm_mma_kernel<<<48, 256, smem_bytes>>>(rel_w2, cr_w2, nullptr, nullptr,
                                             rel_b2, cr_b2, 1);

    heads_kernel<<<480, 256>>>(ner_head_w, ner_head_b, emd_head_w, emd_head_b,
                               rel_w3, rel_b3, cr_w3, cr_b3, out);
}

// round 14
// speedup vs baseline: 1.0813x; 1.0813x over previous
#include <cuda_runtime.h>
#include <cuda_bf16.h>
#include <stdint.h>

#define Bn 2
#define Sn 512
#define Hn 768
#define En 64
#define Mn 64
#define Rn 128
#define SIZE_E 32
#define CLS_ID 101
#define REP_K (2*Hn + SIZE_E)    /* 1568 */
#define REL_K (3*Hn + 2*SIZE_E)  /* 2368 */
#define NEGV (-1e30f)

// activation bf16 plane offsets (elements)
#define A_REP0  0
#define A_REP1  200704
#define A_REPR0 401408
#define A_REPR1 1007616
#define A_H1_0  1613824
#define A_H1_1  1810432
#define A_PLANE 2007040

// ------------------------- device scratch -------------------------
__device__ float d_ctx[Bn*Hn];
__device__ float d_ppool[768*4*Hn];
__device__ int   d_pany[768*4];
__device__ __nv_bfloat16 d_a_hi[A_PLANE];
__device__ __nv_bfloat16 d_a_lo[A_PLANE];
__device__ float d_cpart[2359296];
__device__ float d_hid_ner[128*Hn];
__device__ float d_hid_emd[128*Hn];
__device__ float d_h2_rel[256*Hn];
__device__ float d_h2_cr [256*Hn];

#define S0_ELEM (128*Hn)       /* 98304 */
#define S1_BASE 786432
#define S1_ELEM (256*Hn)       /* 196608 */

// ------------------------- helpers -------------------------
__device__ __forceinline__ uint32_t smem_u32(const void* p) {
    uint32_t r;
    asm("{ .reg .u64 t; cvta.to.shared.u64 t, %1; cvt.u32.u64 %0, t; }" : "=r"(r) : "l"(p));
    return r;
}
__device__ __forceinline__ void ldsm4(uint32_t addr, uint32_t& r0, uint32_t& r1,
                                      uint32_t& r2, uint32_t& r3) {
    asm volatile("ldmatrix.sync.aligned.m8n8.x4.shared.b16 {%0,%1,%2,%3}, [%4];"
                 : "=r"(r0), "=r"(r1), "=r"(r2), "=r"(r3) : "r"(addr));
}
__device__ __forceinline__ void mma16816(float* d, const uint32_t* a, uint32_t b0, uint32_t b1) {
    asm volatile("mma.sync.aligned.m16n8k16.row.col.f32.bf16.bf16.f32 "
        "{%0,%1,%2,%3}, {%4,%5,%6,%7}, {%8,%9}, {%0,%1,%2,%3};"
        : "+f"(d[0]), "+f"(d[1]), "+f"(d[2]), "+f"(d[3])
        : "r"(a[0]), "r"(a[1]), "r"(a[2]), "r"(a[3]), "r"(b0), "r"(b1));
}
__device__ __forceinline__ void cvt_hilo(float4 v, uint2& h, uint2& l)
{
    __nv_bfloat162 hx = __floats2bfloat162_rn(v.x, v.y);
    __nv_bfloat162 hz = __floats2bfloat162_rn(v.z, v.w);
    float2 fx = __bfloat1622float2(hx);
    float2 fz = __bfloat1622float2(hz);
    __nv_bfloat162 lx = __floats2bfloat162_rn(v.x - fx.x, v.y - fx.y);
    __nv_bfloat162 lz = __floats2bfloat162_rn(v.z - fz.x, v.w - fz.y);
    h.x = *(uint32_t*)&hx; h.y = *(uint32_t*)&hz;
    l.x = *(uint32_t*)&lx; l.y = *(uint32_t*)&lz;
}
__device__ __forceinline__ void cvt_store(uint32_t phi, uint32_t plo, float4 v)
{
    uint2 h, l; cvt_hilo(v, h, l);
    asm volatile("st.shared.v2.b32 [%0], {%1, %2};" :: "r"(phi), "r"(h.x), "r"(h.y) : "memory");
    asm volatile("st.shared.v2.b32 [%0], {%1, %2};" :: "r"(plo), "r"(l.x), "r"(l.y) : "memory");
}
__device__ __forceinline__ float4 pool_max4(int span, int cc)
{
    float4 v = *(const float4*)&d_ppool[((size_t)span*4 + 0)*Hn + cc];
    #pragma unroll
    for (int ch = 1; ch < 4; ch++) {
        float4 p = *(const float4*)&d_ppool[((size_t)span*4 + ch)*Hn + cc];
        v.x = fmaxf(v.x, p.x); v.y = fmaxf(v.y, p.y);
        v.z = fmaxf(v.z, p.z); v.w = fmaxf(v.w, p.w);
    }
    return v;
}

// ------------------------- pooled masked max (+ ctx blocks at end) -------------------------
__global__ __launch_bounds__(192) void pool_kernel(
    const int* __restrict__ em, const int* __restrict__ mm,
    const int* __restrict__ rm, const int* __restrict__ fm,
    const int* __restrict__ input_ids,
    const float* __restrict__ emb)
{
    int blk = blockIdx.x;
    int tid = threadIdx.x;
    if (blk >= 192) {
        int b = blk - 192;
        __shared__ int cidx;
        if (tid == 0) cidx = Sn;
        __syncthreads();
        for (int s = tid; s < Sn; s += blockDim.x)
            if (input_ids[b*Sn + s] == CLS_ID) atomicMin(&cidx, s);
        __syncthreads();
        int ci = (cidx == Sn) ? 0 : cidx;
        for (int h = tid; h < Hn; h += blockDim.x)
            d_ctx[b*Hn + h] = emb[((size_t)b*Sn + ci)*Hn + h];
        return;
    }
    const int* masks; int Kspans, sgbase, local;
    if (blk < 32)       { masks = em; Kspans = En; sgbase = 0;   local = blk; }
    else if (blk < 64)  { masks = mm; Kspans = Mn; sgbase = 128; local = blk - 32; }
    else if (blk < 128) { masks = rm; Kspans = Rn; sgbase = 256; local = blk - 64; }
    else                { masks = fm; Kspans = Rn; sgbase = 512; local = blk - 128; }

    int gpb   = Kspans >> 4;
    int b     = local / (gpb*4);
    int rem   = local % (gpb*4);
    int g     = rem >> 2;
    int chunk = rem & 3;
    int s0    = chunk * 128;
    int k0    = g * 16;
    int sg0   = sgbase + b*Kspans + k0;

    __shared__ unsigned mw[128];
    __shared__ unsigned anyw;
    if (tid < 128) mw[tid] = 0u;
    if (tid == 0) anyw = 0u;
    __syncthreads();

    for (int i = tid; i < 16*128; i += 192) {
        int t = i >> 7, sl = i & 127;
        if (masks[(size_t)(b*Kspans + k0 + t)*Sn + s0 + sl] != 0)
            atomicOr(&mw[sl], 1u << t);
    }
    __syncthreads();

    unsigned aw = 0u;
    for (int sl = tid; sl < 128; sl += 192) aw |= mw[sl];
    if (aw) atomicOr(&anyw, aw);
    __syncthreads();

    int h0 = tid * 4;
    float4 acc[16];
    #pragma unroll
    for (int t = 0; t < 16; t++) acc[t] = make_float4(NEGV, NEGV, NEGV, NEGV);

    const float* ebase = emb + ((size_t)b*Sn + s0)*Hn + h0;
    for (int sl = 0; sl < 128; sl++) {
        float4 v = *(const float4*)(ebase + (size_t)sl*Hn);
        unsigned m = mw[sl];
        #pragma unroll
        for (int t = 0; t < 16; t++) {
            if (m & (1u << t)) {
                acc[t].x = fmaxf(acc[t].x, v.x);
                acc[t].y = fmaxf(acc[t].y, v.y);
                acc[t].z = fmaxf(acc[t].z, v.z);
                acc[t].w = fmaxf(acc[t].w, v.w);
            }
        }
    }
    unsigned a = anyw;
    #pragma unroll
    for (int t = 0; t < 16; t++)
        *(float4*)&d_ppool[((size_t)(sg0 + t)*4 + chunk)*Hn + h0] = acc[t];
    if (tid < 16) d_pany[(sg0 + tid)*4 + chunk] = (a >> tid) & 1u;
}

// ------------------------- assemble (combine fused): write bf16 hi/lo planes ----------------
__global__ void assemble_kernel(
    const int* __restrict__ entity_sizes, const int* __restrict__ mention_sizes,
    const int* __restrict__ relations,    const int* __restrict__ references,
    const float* __restrict__ ner_size_emb, const float* __restrict__ emd_size_emb)
{
    int row = blockIdx.x;
    int tid = threadIdx.x;
    if (row < 256) {
        int prob = row >> 7;
        int r = row & 127;
        int b = r >> 6;
        int span = prob*128 + r;
        int sz = (prob ? mention_sizes : entity_sizes)[r];
        const float* se = (prob ? emd_size_emb : ner_size_emb) + (size_t)sz*SIZE_E;
        size_t off = (prob ? A_REP1 : A_REP0) + (size_t)r*REP_K;
        for (int i = tid; i < REP_K/4; i += 256) {
            int c = i * 4; float4 v;
            if (c < Hn)            v = *(const float4*)(d_ctx + b*Hn + c);
            else if (c < 2*Hn)     v = pool_max4(span, c - Hn);
            else                   v = *(const float4*)(se + c - 2*Hn);
            uint2 h, l; cvt_hilo(v, h, l);
            *(uint2*)&d_a_hi[off + c] = h;
            *(uint2*)&d_a_lo[off + c] = l;
        }
    } else {
        int isrel = (row < 512);
        int r = isrel ? row - 256 : row - 512;
        int b = r >> 7;
        int span_ctx = (isrel ? 256 : 512) + r;
        const int*   idxs  = isrel ? relations : references;
        const int*   szs   = isrel ? entity_sizes : mention_sizes;
        const float* semb  = isrel ? ner_size_emb : emd_size_emb;
        int pbase = isrel ? 0 : 128;
        int e1 = idxs[r*2], e2 = idxs[r*2 + 1];
        int span1 = pbase + b*64 + e1, span2 = pbase + b*64 + e2;
        const float* s1 = semb + (size_t)szs[b*64 + e1]*SIZE_E;
        const float* s2 = semb + (size_t)szs[b*64 + e2]*SIZE_E;
        int any = d_pany[span_ctx*4] | d_pany[span_ctx*4+1]
                | d_pany[span_ctx*4+2] | d_pany[span_ctx*4+3];
        size_t off = (isrel ? A_REPR0 : A_REPR1) + (size_t)r*REL_K;
        for (int i = tid; i < REL_K/4; i += 256) {
            int c = i * 4; float4 v;
            if (c < Hn) {
                v = pool_max4(span_ctx, c);
                if (!any) v = make_float4(0.f, 0.f, 0.f, 0.f);
            }
            else if (c < 2*Hn)            v = pool_max4(span1, c - Hn);
            else if (c < 3*Hn)            v = pool_max4(span2, c - 2*Hn);
            else if (c < 3*Hn + SIZE_E)   v = *(const float4*)(s1 + c - 3*Hn);
            else                          v = *(const float4*)(s2 + c - 3*Hn - SIZE_E);
            uint2 h, l; cvt_hilo(v, h, l);
            *(uint2*)&d_a_hi[off + c] = h;
            *(uint2*)&d_a_lo[off + c] = l;
        }
    }
}

// ------------------------- HMMA GEMM: cp.async A planes + W reg-prefetch -------------------
#define PADK 72
#define OFF_AHI 0
#define OFF_ALO (128*PADK*2)
#define OFF_BHI (2*128*PADK*2)
#define OFF_BLO (OFF_BHI + 64*PADK*2)
#define BUFSZ   (OFF_BLO + 64*PADK*2)   /* 55296 */

struct Frag {
    uint32_t ah[2][4], al[2][4], bh[2][4], bl[2][4];
};

__device__ __forceinline__ void load_frag(Frag& f, uint32_t base, int k0,
                                          int wm, int wn, int rA, int cAo, int rB, int cBo)
{
    #pragma unroll
    for (int mi = 0; mi < 2; mi++) {
        uint32_t oa = (uint32_t)((wm*32 + mi*16 + rA) * PADK + k0 + cAo) * 2;
        ldsm4(base + OFF_AHI + oa, f.ah[mi][0], f.ah[mi][1], f.ah[mi][2], f.ah[mi][3]);
        ldsm4(base + OFF_ALO + oa, f.al[mi][0], f.al[mi][1], f.al[mi][2], f.al[mi][3]);
    }
    #pragma unroll
    for (int bi = 0; bi < 2; bi++) {
        uint32_t ob = (uint32_t)((wn*32 + bi*16 + rB) * PADK + k0 + cBo) * 2;
        ldsm4(base + OFF_BHI + ob, f.bh[bi][0], f.bh[bi][1], f.bh[bi][2], f.bh[bi][3]);
        ldsm4(base + OFF_BLO + ob, f.bl[bi][0], f.bl[bi][1], f.bl[bi][2], f.bl[bi][3]);
    }
}

// three full sweeps: same-accumulator HMMAs separated by 7 independent HMMAs.
// per-accumulator summation order (hh -> hl -> lh) unchanged => numerics identical.
__device__ __forceinline__ void do_mma(float acc[2][4][4], const Frag& f)
{
    #pragma unroll
    for (int mi = 0; mi < 2; mi++)
        #pragma unroll
        for (int ni = 0; ni < 4; ni++) {
            int bi = ni >> 1, p = (ni & 1) * 2;
            mma16816(acc[mi][ni], f.ah[mi], f.bh[bi][p], f.bh[bi][p+1]);
        }
    #pragma unroll
    for (int mi = 0; mi < 2; mi++)
        #pragma unroll
        for (int ni = 0; ni < 4; ni++) {
            int bi = ni >> 1, p = (ni & 1) * 2;
            mma16816(acc[mi][ni], f.ah[mi], f.bl[bi][p], f.bl[bi][p+1]);
        }
    #pragma unroll
    for (int mi = 0; mi < 2; mi++)
        #pragma unroll
        for (int ni = 0; ni < 4; ni++) {
            int bi = ni >> 1, p = (ni & 1) * 2;
            mma16816(acc[mi][ni], f.al[mi], f.bh[bi][p], f.bh[bi][p+1]);
        }
}

__device__ __forceinline__ void cp_async_A(
    uint32_t base, const __nv_bfloat16* Ah, const __nv_bfloat16* Al,
    int K, int m0, int kb, int tid)
{
    #pragma unroll
    for (int i = 0; i < 4; i++) {
        int u = tid + (i << 8);
        int arow = u >> 3, c16 = u & 7;
        uint32_t o = (uint32_t)arow * (PADK*2) + c16*16;
        const __nv_bfloat16* ph = Ah + (size_t)(m0 + arow)*K + kb + c16*8;
        const __nv_bfloat16* pl = Al + (size_t)(m0 + arow)*K + kb + c16*8;
        asm volatile("cp.async.ca.shared.global [%0], [%1], 16;"
                     :: "r"(base + OFF_AHI + o), "l"(ph) : "memory");
        asm volatile("cp.async.ca.shared.global [%0], [%1], 16;"
                     :: "r"(base + OFF_ALO + o), "l"(pl) : "memory");
    }
    asm volatile("cp.async.commit_group;" ::: "memory");
}

__device__ __forceinline__ void ldg_W(float4 (&wbuf)[4], const float* W,
                                      int K, int n0, int kb, int wrow, int c4)
{
    int kc = K - kb; if (kc > 64) kc = 64;
    #pragma unroll
    for (int i = 0; i < 4; i++)
        if (c4 < kc)
            wbuf[i] = *(const float4*)(W + (size_t)(n0 + wrow + i*16)*K + kb + c4);
}

__global__ __launch_bounds__(256, 2) void gemm_mma_kernel(
    const float* __restrict__ Wa, const float* __restrict__ Wb,
    const float* __restrict__ Wc, const float* __restrict__ Wd,
    int mode)
{
    extern __shared__ char smem[];
    uint32_t sb = smem_u32(smem);
    int tid = threadIdx.x;
    int wid = tid >> 5, lane = tid & 31;
    int wm = wid & 3, wn = wid >> 2;

    // resolve job
    const __nv_bfloat16 *Ah, *Al; const float* W; float* Out;
    int K, m0, n0, c0, c1;
    int bx = blockIdx.x;
    if (mode == 0 && bx < 96) {
        int prob = bx / 48, r = bx % 48, nt = r >> 2, sp = r & 3;
        size_t aoff = prob ? A_REP1 : A_REP0;
        Ah = d_a_hi + aoff; Al = d_a_lo + aoff;
        W = prob ? Wb : Wa;
        Out = d_cpart + (size_t)(prob*4 + sp) * S0_ELEM;
        K = REP_K; m0 = 0; n0 = nt * 64;
        int nc = (K + 63) >> 6;
        c0 = sp * nc / 4; c1 = (sp + 1) * nc / 4;
    } else if (mode == 0) {
        int i = bx - 96;
        int prob = i / 96, r = i % 96;
        int mt = r / 48, r2 = r % 48, nt = r2 >> 2, sp = r2 & 3;
        size_t aoff = prob ? A_REPR1 : A_REPR0;
        Ah = d_a_hi + aoff; Al = d_a_lo + aoff;
        W = prob ? Wd : Wc; K = REL_K;
        Out = d_cpart + S1_BASE + (size_t)(prob*4 + sp) * S1_ELEM;
        m0 = mt * 128; n0 = nt * 64;
        int nc = (K + 63) >> 6;
        c0 = sp * nc / 4; c1 = (sp + 1) * nc / 4;
    } else {
        int i = bx;
        int prob = i / 48, r = i % 48;
        int mt = r / 24, r2 = r % 24, nt = r2 >> 1, sp = r2 & 1;
        size_t aoff = prob ? A_H1_1 : A_H1_0;
        Ah = d_a_hi + aoff; Al = d_a_lo + aoff;
        W = prob ? Wb : Wa; K = Hn;
        Out = d_cpart + (size_t)(prob*2 + sp) * S1_ELEM;
        m0 = mt * 128; n0 = nt * 64;
        c0 = sp * 6; c1 = (sp + 1) * 6;
    }

    int wrow_ld = tid >> 4, wc4_ld = (tid & 15) << 2;

    float acc[2][4][4];
    #pragma unroll
    for (int mi = 0; mi < 2; mi++)
        #pragma unroll
        for (int ni = 0; ni < 4; ni++)
            #pragma unroll
            for (int q = 0; q < 4; q++) acc[mi][ni][q] = 0.f;

    int g = lane >> 3;
    int rA = (lane & 7) + ((g & 1) << 3);
    int cAo = (g & 2) << 2;
    int rB = (lane & 7) + ((g & 2) << 2);
    int cBo = (g & 1) << 3;

    Frag f0;
    float4 wbuf[4];

    // prologue: W(c0) into registers; cp.async A(c0)
    ldg_W(wbuf, W, K, n0, c0 << 6, wrow_ld, wc4_ld);
    cp_async_A(sb + (uint32_t)(c0 & 1) * BUFSZ, Ah, Al, K, m0, c0 << 6, tid);

    for (int c = c0; c < c1; c++) {
        uint32_t base = sb + (uint32_t)(c & 1) * BUFSZ;

        // store W(c) from registers (cvt inline)
        {
            uint32_t o = (uint32_t)(wrow_ld * PADK + wc4_ld) * 2;
            #pragma unroll
            for (int i = 0; i < 4; i++)
                cvt_store(base + OFF_BHI + o + i*16*PADK*2,
                          base + OFF_BLO + o + i*16*PADK*2, wbuf[i]);
        }

        asm volatile("cp.async.wait_group 0;" ::: "memory");
        __syncthreads();   // A(c) + W(c) visible; all warps done with MMA(c-1)

        // issue next chunk's loads (covered by MMA below)
        if (c + 1 < c1) {
            cp_async_A(sb + (uint32_t)((c + 1) & 1) * BUFSZ, Ah, Al, K, m0, (c + 1) << 6, tid);
            ldg_W(wbuf, W, K, n0, (c + 1) << 6, wrow_ld, wc4_ld);
        }

        int kc = K - (c << 6); if (kc > 64) kc = 64;
        int steps = kc >> 4;
        #pragma unroll 4
        for (int s = 0; s < steps; s++) {
            load_frag(f0, base, s << 4, wm, wn, rA, cAo, rB, cBo);
            do_mma(acc, f0);
        }
    }

    // epilogue: raw partial store
    int r0 = lane >> 2, cq = (lane & 3) * 2;
    #pragma unroll
    for (int mi = 0; mi < 2; mi++) {
        #pragma unroll
        for (int ni = 0; ni < 4; ni++) {
            int col = n0 + wn*32 + ni*8 + cq;
            int row = m0 + wm*32 + mi*16 + r0;
            float2 v0 = make_float2(acc[mi][ni][0], acc[mi][ni][1]);
            float2 v1 = make_float2(acc[mi][ni][2], acc[mi][ni][3]);
            *(float2*)(Out + (size_t)row * Hn + col) = v0;
            *(float2*)(Out + (size_t)(row + 8) * Hn + col) = v1;
        }
    }
}

// ------------------------- finalize A: stage0 (fp32 hid) + stage1 (bf16 h1 planes) ----------
__global__ void finalizeA_kernel(
    const float* __restrict__ b_ner, const float* __restrict__ b_emd,
    const float* __restrict__ b_rel, const float* __restrict__ b_cr)
{
    int prob = blockIdx.y;
    int idx4 = (blockIdx.x * 256 + threadIdx.x) * 4;
    if (idx4 < S0_ELEM) {
        const float* p = d_cpart + (size_t)(prob*4) * S0_ELEM + idx4;
        float4 a = *(const float4*)p;
        float4 b = *(const float4*)(p + S0_ELEM);
        float4 c = *(const float4*)(p + 2*(size_t)S0_ELEM);
        float4 d = *(const float4*)(p + 3*(size_t)S0_ELEM);
        float4 bb = *(const float4*)((prob ? b_emd : b_ner) + (idx4 % Hn));
        float4 r;
        r.x = fmaxf((a.x + b.x) + (c.x + d.x) + bb.x, 0.f);
        r.y = fmaxf((a.y + b.y) + (c.y + d.y) + bb.y, 0.f);
        r.z = fmaxf((a.z + b.z) + (c.z + d.z) + bb.z, 0.f);
        r.w = fmaxf((a.w + b.w) + (c.w + d.w) + bb.w, 0.f);
        *(float4*)((prob ? d_hid_emd : d_hid_ner) + idx4) = r;
    } else {
        int j = idx4 - S0_ELEM;
        if (j >= S1_ELEM) return;
        const float* p = d_cpart + S1_BASE + (size_t)(prob*4) * S1_ELEM + j;
        float4 a = *(const float4*)p;
        float4 b = *(const float4*)(p + S1_ELEM);
        float4 c = *(const float4*)(p + 2*(size_t)S1_ELEM);
        float4 d = *(const float4*)(p + 3*(size_t)S1_ELEM);
        float4 bb = *(const float4*)((prob ? b_cr : b_rel) + (j % Hn));
        float4 r;
        r.x = fmaxf((a.x + b.x) + (c.x + d.x) + bb.x, 0.f);
        r.y = fmaxf((a.y + b.y) + (c.y + d.y) + bb.y, 0.f);
        r.z = fmaxf((a.z + b.z) + (c.z + d.z) + bb.z, 0.f);
        r.w = fmaxf((a.w + b.w) + (c.w + d.w) + bb.w, 0.f);
        uint2 h, l; cvt_hilo(r, h, l);
        size_t off = (prob ? A_H1_1 : A_H1_0) + j;
        *(uint2*)&d_a_hi[off] = h;
        *(uint2*)&d_a_lo[off] = l;
    }
}

// ------------------------- finalize B: stage2 (sum 2 splits, fp32 h2) -------------------------
__global__ void finalizeB_kernel(
    const float* __restrict__ b_rel, const float* __restrict__ b_cr)
{
    int prob = blockIdx.y;
    int idx4 = (blockIdx.x * 256 + threadIdx.x) * 4;
    if (idx4 >= S1_ELEM) return;
    const float* p = d_cpart + (size_t)(prob*2) * S1_ELEM + idx4;
    float4 a = *(const float4*)p;
    float4 b = *(const float4*)(p + S1_ELEM);
    float4 bb = *(const float4*)((prob ? b_cr : b_rel) + (idx4 % Hn));
    float4 r;
    r.x = fmaxf(a.x + b.x + bb.x, 0.f);
    r.y = fmaxf(a.y + b.y + bb.y, 0.f);
    r.z = fmaxf(a.z + b.z + bb.z, 0.f);
    r.w = fmaxf(a.w + b.w + bb.w, 0.f);
    *(float4*)((prob ? d_h2_cr : d_h2_rel) + idx4) = r;
}

// ------------------------- heads -------------------------
__global__ void heads_kernel(
    const float* __restrict__ ner_hw, const float* __restrict__ ner_hb,
    const float* __restrict__ emd_hw, const float* __restrict__ emd_hb,
    const float* __restrict__ rel_w3, const float* __restrict__ rel_b3,
    const float* __restrict__ cr_w3,  const float* __restrict__ cr_b3,
    float* __restrict__ out)
{
    int gwarp = (blockIdx.x * blockDim.x + threadIdx.x) >> 5;
    int lane = threadIdx.x & 31;
    if (gwarp >= 3840) return;
    const float* A; const float* Wr; float bias;
    if (gwarp < 1280) {
        int r = gwarp / 10, n = gwarp % 10;
        A = d_hid_ner + (size_t)r*Hn; Wr = ner_hw + (size_t)n*Hn; bias = ner_hb[n];
    } else if (gwarp < 3328) {
        int i = gwarp - 1280; int r = i / 8, n = i % 8;
        A = d_h2_rel + (size_t)r*Hn; Wr = rel_w3 + (size_t)n*Hn; bias = rel_b3[n];
    } else if (gwarp < 3584) {
        int i = gwarp - 3328; int r = i / 2, n = i & 1;
        A = d_hid_emd + (size_t)r*Hn; Wr = emd_hw + (size_t)n*Hn; bias = emd_hb[n];
    } else {
        int i = gwarp - 3584;
        A = d_h2_cr + (size_t)i*Hn; Wr = cr_w3; bias = cr_b3[0];
    }
    float s = 0.f;
    for (int k = lane*4; k < Hn; k += 128) {
        float4 a = *(const float4*)(A + k);
        float4 w = *(const float4*)(Wr + k);
        s += a.x*w.x + a.y*w.y + a.z*w.z + a.w*w.w;
    }
    #pragma unroll
    for (int o = 16; o; o >>= 1) s += __shfl_xor_sync(0xffffffffu, s, o);
    if (lane == 0) out[gwarp] = s + bias;
}

// ------------------------- launch -------------------------
extern "C" void kernel_launch(void* const* d_in, const int* in_sizes, int n_in,
                              void* d_out, int out_size)
{
    const int*   input_ids       = (const int*)  d_in[0];
    const int*   entity_masks    = (const int*)  d_in[1];
    const int*   entity_sizes    = (const int*)  d_in[2];
    const int*   mention_masks   = (const int*)  d_in[3];
    const int*   mention_sizes   = (const int*)  d_in[4];
    const int*   relations       = (const int*)  d_in[5];
    const int*   rel_masks       = (const int*)  d_in[6];
    const int*   references      = (const int*)  d_in[7];
    const int*   references_masks= (const int*)  d_in[8];
    const float* emb             = (const float*)d_in[9];
    const float* ner_size_emb    = (const float*)d_in[10];
    const float* emd_size_emb    = (const float*)d_in[11];
    const float* ner_rep_w = (const float*)d_in[12]; const float* ner_rep_b = (const float*)d_in[13];
    const float* ner_head_w= (const float*)d_in[14]; const float* ner_head_b= (const float*)d_in[15];
    const float* emd_rep_w = (const float*)d_in[16]; const float* emd_rep_b = (const float*)d_in[17];
    const float* emd_head_w= (const float*)d_in[18]; const float* emd_head_b= (const float*)d_in[19];
    const float* rel_w1 = (const float*)d_in[20]; const float* rel_b1 = (const float*)d_in[21];
    const float* rel_w2 = (const float*)d_in[22]; const float* rel_b2 = (const float*)d_in[23];
    const float* rel_w3 = (const float*)d_in[24]; const float* rel_b3 = (const float*)d_in[25];
    const float* cr_w1  = (const float*)d_in[26]; const float* cr_b1  = (const float*)d_in[27];
    const float* cr_w2  = (const float*)d_in[28]; const float* cr_b2  = (const float*)d_in[29];
    const float* cr_w3  = (const float*)d_in[30]; const float* cr_b3  = (const float*)d_in[31];
    float* out = (float*)d_out;

    const int smem_bytes = 2 * BUFSZ;   // 110592/CTA; 2 CTA/SM
    cudaFuncSetAttribute(gemm_mma_kernel, cudaFuncAttributeMaxDynamicSharedMemorySize, smem_bytes);

    pool_kernel<<<194, 192>>>(entity_masks, mention_masks, rel_masks, references_masks,
                              input_ids, emb);
    assemble_kernel<<<768, 256>>>(entity_sizes, mention_sizes, relations, references,
                                  ner_size_emb, emd_size_emb);

    // launch 1: stage0 split-K4 (96) + stage1 split-K4 (192) = 288 CTAs
    gemm_mma_kernel<<<288, 256, smem_bytes>>>(ner_rep_w, emd_rep_w, rel_w1, cr_w1, 0);
    {
        dim3 f((S0_ELEM + S1_ELEM)/1024, 2);
        finalizeA_kernel<<<f, 256>>>(ner_rep_b, emd_rep_b, rel_b1, cr_b1);
    }

    // launch 2: stage2 split-K2 (96 CTAs)
    gemm_mma_kernel<<<96, 256, smem_bytes>>>(rel_w2, cr_w2, nullptr, nullptr, 1);
    {
        dim3 f(S1_ELEM/1024, 2);
        finalizeB_kernel<<<f, 256>>>(rel_b2, cr_b2);
    }

    heads_kernel<<<480, 256>>>(ner_head_w, ner_head_b, emd_head_w, emd_head_b,
                               rel_w3, rel_b3, cr_w3, cr_b3, out);
}

// round 15
// speedup vs baseline: 1.0841x; 1.0025x over previous
#include <cuda_runtime.h>
#include <cuda_bf16.h>
#include <stdint.h>

#define Bn 2
#define Sn 512
#define Hn 768
#define En 64
#define Mn 64
#define Rn 128
#define SIZE_E 32
#define CLS_ID 101
#define REP_K (2*Hn + SIZE_E)    /* 1568 */
#define REL_K (3*Hn + 2*SIZE_E)  /* 2368 */
#define NEGV (-1e30f)

// activation bf16 plane offsets (elements)
#define A_REP0  0
#define A_REP1  200704
#define A_REPR0 401408
#define A_REPR1 1007616
#define A_H1_0  1613824
#define A_H1_1  1810432
#define A_PLANE 2007040

// ------------------------- device scratch -------------------------
__device__ float d_ctx[Bn*Hn];
__device__ float d_ppool[768*4*Hn];
__device__ int   d_pany[768*4];
__device__ __nv_bfloat16 d_a_hi[A_PLANE];
__device__ __nv_bfloat16 d_a_lo[A_PLANE];
__device__ float d_cpart[2359296];
__device__ float d_hid_ner[128*Hn];
__device__ float d_hid_emd[128*Hn];
__device__ float d_h2_rel[256*Hn];
__device__ float d_h2_cr [256*Hn];

#define S0_ELEM (128*Hn)       /* 98304 */
#define S1_BASE 786432
#define S1_ELEM (256*Hn)       /* 196608 */

// ------------------------- helpers -------------------------
__device__ __forceinline__ uint32_t smem_u32(const void* p) {
    uint32_t r;
    asm("{ .reg .u64 t; cvta.to.shared.u64 t, %1; cvt.u32.u64 %0, t; }" : "=r"(r) : "l"(p));
    return r;
}
__device__ __forceinline__ void ldsm4(uint32_t addr, uint32_t& r0, uint32_t& r1,
                                      uint32_t& r2, uint32_t& r3) {
    asm volatile("ldmatrix.sync.aligned.m8n8.x4.shared.b16 {%0,%1,%2,%3}, [%4];"
                 : "=r"(r0), "=r"(r1), "=r"(r2), "=r"(r3) : "r"(addr));
}
__device__ __forceinline__ void mma16816(float* d, const uint32_t* a, uint32_t b0, uint32_t b1) {
    asm volatile("mma.sync.aligned.m16n8k16.row.col.f32.bf16.bf16.f32 "
        "{%0,%1,%2,%3}, {%4,%5,%6,%7}, {%8,%9}, {%0,%1,%2,%3};"
        : "+f"(d[0]), "+f"(d[1]), "+f"(d[2]), "+f"(d[3])
        : "r"(a[0]), "r"(a[1]), "r"(a[2]), "r"(a[3]), "r"(b0), "r"(b1));
}
__device__ __forceinline__ void cvt_hilo(float4 v, uint2& h, uint2& l)
{
    __nv_bfloat162 hx = __floats2bfloat162_rn(v.x, v.y);
    __nv_bfloat162 hz = __floats2bfloat162_rn(v.z, v.w);
    float2 fx = __bfloat1622float2(hx);
    float2 fz = __bfloat1622float2(hz);
    __nv_bfloat162 lx = __floats2bfloat162_rn(v.x - fx.x, v.y - fx.y);
    __nv_bfloat162 lz = __floats2bfloat162_rn(v.z - fz.x, v.w - fz.y);
    h.x = *(uint32_t*)&hx; h.y = *(uint32_t*)&hz;
    l.x = *(uint32_t*)&lx; l.y = *(uint32_t*)&lz;
}
__device__ __forceinline__ void cvt_store(uint32_t phi, uint32_t plo, float4 v)
{
    uint2 h, l; cvt_hilo(v, h, l);
    asm volatile("st.shared.v2.b32 [%0], {%1, %2};" :: "r"(phi), "r"(h.x), "r"(h.y) : "memory");
    asm volatile("st.shared.v2.b32 [%0], {%1, %2};" :: "r"(plo), "r"(l.x), "r"(l.y) : "memory");
}
__device__ __forceinline__ float4 pool_max4(int span, int cc)
{
    float4 v = *(const float4*)&d_ppool[((size_t)span*4 + 0)*Hn + cc];
    #pragma unroll
    for (int ch = 1; ch < 4; ch++) {
        float4 p = *(const float4*)&d_ppool[((size_t)span*4 + ch)*Hn + cc];
        v.x = fmaxf(v.x, p.x); v.y = fmaxf(v.y, p.y);
        v.z = fmaxf(v.z, p.z); v.w = fmaxf(v.w, p.w);
    }
    return v;
}

// ------------------------- pooled masked max (+ ctx blocks at end) -------------------------
__global__ __launch_bounds__(192) void pool_kernel(
    const int* __restrict__ em, const int* __restrict__ mm,
    const int* __restrict__ rm, const int* __restrict__ fm,
    const int* __restrict__ input_ids,
    const float* __restrict__ emb)
{
    int blk = blockIdx.x;
    int tid = threadIdx.x;
    if (blk >= 192) {
        int b = blk - 192;
        __shared__ int cidx;
        if (tid == 0) cidx = Sn;
        __syncthreads();
        for (int s = tid; s < Sn; s += blockDim.x)
            if (input_ids[b*Sn + s] == CLS_ID) atomicMin(&cidx, s);
        __syncthreads();
        int ci = (cidx == Sn) ? 0 : cidx;
        for (int h = tid; h < Hn; h += blockDim.x)
            d_ctx[b*Hn + h] = emb[((size_t)b*Sn + ci)*Hn + h];
        return;
    }
    const int* masks; int Kspans, sgbase, local;
    if (blk < 32)       { masks = em; Kspans = En; sgbase = 0;   local = blk; }
    else if (blk < 64)  { masks = mm; Kspans = Mn; sgbase = 128; local = blk - 32; }
    else if (blk < 128) { masks = rm; Kspans = Rn; sgbase = 256; local = blk - 64; }
    else                { masks = fm; Kspans = Rn; sgbase = 512; local = blk - 128; }

    int gpb   = Kspans >> 4;
    int b     = local / (gpb*4);
    int rem   = local % (gpb*4);
    int g     = rem >> 2;
    int chunk = rem & 3;
    int s0    = chunk * 128;
    int k0    = g * 16;
    int sg0   = sgbase + b*Kspans + k0;

    __shared__ unsigned mw[128];
    __shared__ unsigned anyw;
    if (tid < 128) mw[tid] = 0u;
    if (tid == 0) anyw = 0u;
    __syncthreads();

    for (int i = tid; i < 16*128; i += 192) {
        int t = i >> 7, sl = i & 127;
        if (masks[(size_t)(b*Kspans + k0 + t)*Sn + s0 + sl] != 0)
            atomicOr(&mw[sl], 1u << t);
    }
    __syncthreads();

    unsigned aw = 0u;
    for (int sl = tid; sl < 128; sl += 192) aw |= mw[sl];
    if (aw) atomicOr(&anyw, aw);
    __syncthreads();

    int h0 = tid * 4;
    float4 acc[16];
    #pragma unroll
    for (int t = 0; t < 16; t++) acc[t] = make_float4(NEGV, NEGV, NEGV, NEGV);

    const float* ebase = emb + ((size_t)b*Sn + s0)*Hn + h0;
    for (int sl = 0; sl < 128; sl++) {
        float4 v = *(const float4*)(ebase + (size_t)sl*Hn);
        unsigned m = mw[sl];
        #pragma unroll
        for (int t = 0; t < 16; t++) {
            if (m & (1u << t)) {
                acc[t].x = fmaxf(acc[t].x, v.x);
                acc[t].y = fmaxf(acc[t].y, v.y);
                acc[t].z = fmaxf(acc[t].z, v.z);
                acc[t].w = fmaxf(acc[t].w, v.w);
            }
        }
    }
    unsigned a = anyw;
    #pragma unroll
    for (int t = 0; t < 16; t++)
        *(float4*)&d_ppool[((size_t)(sg0 + t)*4 + chunk)*Hn + h0] = acc[t];
    if (tid < 16) d_pany[(sg0 + tid)*4 + chunk] = (a >> tid) & 1u;
}

// ------------------------- assemble (combine fused): write bf16 hi/lo planes ----------------
__global__ void assemble_kernel(
    const int* __restrict__ entity_sizes, const int* __restrict__ mention_sizes,
    const int* __restrict__ relations,    const int* __restrict__ references,
    const float* __restrict__ ner_size_emb, const float* __restrict__ emd_size_emb)
{
    int row = blockIdx.x;
    int tid = threadIdx.x;
    if (row < 256) {
        int prob = row >> 7;
        int r = row & 127;
        int b = r >> 6;
        int span = prob*128 + r;
        int sz = (prob ? mention_sizes : entity_sizes)[r];
        const float* se = (prob ? emd_size_emb : ner_size_emb) + (size_t)sz*SIZE_E;
        size_t off = (prob ? A_REP1 : A_REP0) + (size_t)r*REP_K;
        for (int i = tid; i < REP_K/4; i += 256) {
            int c = i * 4; float4 v;
            if (c < Hn)            v = *(const float4*)(d_ctx + b*Hn + c);
            else if (c < 2*Hn)     v = pool_max4(span, c - Hn);
            else                   v = *(const float4*)(se + c - 2*Hn);
            uint2 h, l; cvt_hilo(v, h, l);
            *(uint2*)&d_a_hi[off + c] = h;
            *(uint2*)&d_a_lo[off + c] = l;
        }
    } else {
        int isrel = (row < 512);
        int r = isrel ? row - 256 : row - 512;
        int b = r >> 7;
        int span_ctx = (isrel ? 256 : 512) + r;
        const int*   idxs  = isrel ? relations : references;
        const int*   szs   = isrel ? entity_sizes : mention_sizes;
        const float* semb  = isrel ? ner_size_emb : emd_size_emb;
        int pbase = isrel ? 0 : 128;
        int e1 = idxs[r*2], e2 = idxs[r*2 + 1];
        int span1 = pbase + b*64 + e1, span2 = pbase + b*64 + e2;
        const float* s1 = semb + (size_t)szs[b*64 + e1]*SIZE_E;
        const float* s2 = semb + (size_t)szs[b*64 + e2]*SIZE_E;
        int any = d_pany[span_ctx*4] | d_pany[span_ctx*4+1]
                | d_pany[span_ctx*4+2] | d_pany[span_ctx*4+3];
        size_t off = (isrel ? A_REPR0 : A_REPR1) + (size_t)r*REL_K;
        for (int i = tid; i < REL_K/4; i += 256) {
            int c = i * 4; float4 v;
            if (c < Hn) {
                v = pool_max4(span_ctx, c);
                if (!any) v = make_float4(0.f, 0.f, 0.f, 0.f);
            }
            else if (c < 2*Hn)            v = pool_max4(span1, c - Hn);
            else if (c < 3*Hn)            v = pool_max4(span2, c - 2*Hn);
            else if (c < 3*Hn + SIZE_E)   v = *(const float4*)(s1 + c - 3*Hn);
            else                          v = *(const float4*)(s2 + c - 3*Hn - SIZE_E);
            uint2 h, l; cvt_hilo(v, h, l);
            *(uint2*)&d_a_hi[off + c] = h;
            *(uint2*)&d_a_lo[off + c] = l;
        }
    }
}

// ------------------------- HMMA GEMM: cp.async A planes + W reg-prefetch -------------------
#define PADK 72
#define OFF_AHI 0
#define OFF_ALO (128*PADK*2)
#define OFF_BHI (2*128*PADK*2)
#define OFF_BLO (OFF_BHI + 64*PADK*2)
#define BUFSZ   (OFF_BLO + 64*PADK*2)   /* 55296 */

struct Frag {
    uint32_t ah[2][4], al[2][4], bh[2][4], bl[2][4];
};

__device__ __forceinline__ void load_frag(Frag& f, uint32_t base, int k0,
                                          int wm, int wn, int rA, int cAo, int rB, int cBo)
{
    #pragma unroll
    for (int mi = 0; mi < 2; mi++) {
        uint32_t oa = (uint32_t)((wm*32 + mi*16 + rA) * PADK + k0 + cAo) * 2;
        ldsm4(base + OFF_AHI + oa, f.ah[mi][0], f.ah[mi][1], f.ah[mi][2], f.ah[mi][3]);
        ldsm4(base + OFF_ALO + oa, f.al[mi][0], f.al[mi][1], f.al[mi][2], f.al[mi][3]);
    }
    #pragma unroll
    for (int bi = 0; bi < 2; bi++) {
        uint32_t ob = (uint32_t)((wn*32 + bi*16 + rB) * PADK + k0 + cBo) * 2;
        ldsm4(base + OFF_BHI + ob, f.bh[bi][0], f.bh[bi][1], f.bh[bi][2], f.bh[bi][3]);
        ldsm4(base + OFF_BLO + ob, f.bl[bi][0], f.bl[bi][1], f.bl[bi][2], f.bl[bi][3]);
    }
}

// three full sweeps: same-accumulator HMMAs separated by 7 independent HMMAs.
// per-accumulator summation order (hh -> hl -> lh) unchanged => numerics identical.
__device__ __forceinline__ void do_mma(float acc[2][4][4], const Frag& f)
{
    #pragma unroll
    for (int mi = 0; mi < 2; mi++)
        #pragma unroll
        for (int ni = 0; ni < 4; ni++) {
            int bi = ni >> 1, p = (ni & 1) * 2;
            mma16816(acc[mi][ni], f.ah[mi], f.bh[bi][p], f.bh[bi][p+1]);
        }
    #pragma unroll
    for (int mi = 0; mi < 2; mi++)
        #pragma unroll
        for (int ni = 0; ni < 4; ni++) {
            int bi = ni >> 1, p = (ni & 1) * 2;
            mma16816(acc[mi][ni], f.ah[mi], f.bl[bi][p], f.bl[bi][p+1]);
        }
    #pragma unroll
    for (int mi = 0; mi < 2; mi++)
        #pragma unroll
        for (int ni = 0; ni < 4; ni++) {
            int bi = ni >> 1, p = (ni & 1) * 2;
            mma16816(acc[mi][ni], f.al[mi], f.bh[bi][p], f.bh[bi][p+1]);
        }
}

__device__ __forceinline__ void cp_async_A(
    uint32_t base, const __nv_bfloat16* Ah, const __nv_bfloat16* Al,
    int K, int m0, int kb, int tid)
{
    #pragma unroll
    for (int i = 0; i < 4; i++) {
        int u = tid + (i << 8);
        int arow = u >> 3, c16 = u & 7;
        uint32_t o = (uint32_t)arow * (PADK*2) + c16*16;
        const __nv_bfloat16* ph = Ah + (size_t)(m0 + arow)*K + kb + c16*8;
        const __nv_bfloat16* pl = Al + (size_t)(m0 + arow)*K + kb + c16*8;
        asm volatile("cp.async.ca.shared.global [%0], [%1], 16;"
                     :: "r"(base + OFF_AHI + o), "l"(ph) : "memory");
        asm volatile("cp.async.ca.shared.global [%0], [%1], 16;"
                     :: "r"(base + OFF_ALO + o), "l"(pl) : "memory");
    }
    asm volatile("cp.async.commit_group;" ::: "memory");
}

__device__ __forceinline__ void ldg_W(float4 (&wbuf)[4], const float* W,
                                      int K, int n0, int kb, int wrow, int c4)
{
    int kc = K - kb; if (kc > 64) kc = 64;
    #pragma unroll
    for (int i = 0; i < 4; i++)
        if (c4 < kc)
            wbuf[i] = *(const float4*)(W + (size_t)(n0 + wrow + i*16)*K + kb + c4);
}

__global__ __launch_bounds__(256, 2) void gemm_mma_kernel(
    const float* __restrict__ Wa, const float* __restrict__ Wb,
    const float* __restrict__ Wc, const float* __restrict__ Wd,
    int mode)
{
    extern __shared__ char smem[];
    uint32_t sb = smem_u32(smem);
    int tid = threadIdx.x;
    int wid = tid >> 5, lane = tid & 31;
    int wm = wid & 3, wn = wid >> 2;

    // resolve job (split-K2 everywhere)
    const __nv_bfloat16 *Ah, *Al; const float* W; float* Out;
    int K, m0, n0, c0, c1;
    int bx = blockIdx.x;
    if (mode == 0 && bx < 48) {
        // stage0: 2 probs x 12 n-tiles x 2 splits
        int prob = bx / 24, r = bx % 24, nt = r >> 1, sp = r & 1;
        size_t aoff = prob ? A_REP1 : A_REP0;
        Ah = d_a_hi + aoff; Al = d_a_lo + aoff;
        W = prob ? Wb : Wa;
        Out = d_cpart + (size_t)(prob*2 + sp) * S0_ELEM;
        K = REP_K; m0 = 0; n0 = nt * 64;
        int nc = (K + 63) >> 6;   // 25
        c0 = sp * nc / 2; c1 = (sp + 1) * nc / 2;
    } else if (mode == 0) {
        // stage1: 2 probs x 2 m-tiles x 12 n-tiles x 2 splits (96 CTAs)
        int i = bx - 48;
        int prob = i / 48, r = i % 48;
        int mt = r / 24, r2 = r % 24, nt = r2 >> 1, sp = r2 & 1;
        size_t aoff = prob ? A_REPR1 : A_REPR0;
        Ah = d_a_hi + aoff; Al = d_a_lo + aoff;
        W = prob ? Wd : Wc; K = REL_K;
        Out = d_cpart + S1_BASE + (size_t)(prob*2 + sp) * S1_ELEM;
        m0 = mt * 128; n0 = nt * 64;
        int nc = (K + 63) >> 6;   // 37
        c0 = sp * nc / 2; c1 = (sp + 1) * nc / 2;
    } else {
        // stage2: 2 probs x 2 m-tiles x 12 n-tiles x 2 splits (96 CTAs)
        int i = bx;
        int prob = i / 48, r = i % 48;
        int mt = r / 24, r2 = r % 24, nt = r2 >> 1, sp = r2 & 1;
        size_t aoff = prob ? A_H1_1 : A_H1_0;
        Ah = d_a_hi + aoff; Al = d_a_lo + aoff;
        W = prob ? Wb : Wa; K = Hn;
        Out = d_cpart + (size_t)(prob*2 + sp) * S1_ELEM;
        m0 = mt * 128; n0 = nt * 64;
        c0 = sp * 6; c1 = (sp + 1) * 6;
    }

    int wrow_ld = tid >> 4, wc4_ld = (tid & 15) << 2;

    float acc[2][4][4];
    #pragma unroll
    for (int mi = 0; mi < 2; mi++)
        #pragma unroll
        for (int ni = 0; ni < 4; ni++)
            #pragma unroll
            for (int q = 0; q < 4; q++) acc[mi][ni][q] = 0.f;

    int g = lane >> 3;
    int rA = (lane & 7) + ((g & 1) << 3);
    int cAo = (g & 2) << 2;
    int rB = (lane & 7) + ((g & 2) << 2);
    int cBo = (g & 1) << 3;

    Frag f0;
    float4 wbuf[4];

    // prologue: W(c0) into registers; cp.async A(c0)
    ldg_W(wbuf, W, K, n0, c0 << 6, wrow_ld, wc4_ld);
    cp_async_A(sb + (uint32_t)(c0 & 1) * BUFSZ, Ah, Al, K, m0, c0 << 6, tid);

    for (int c = c0; c < c1; c++) {
        uint32_t base = sb + (uint32_t)(c & 1) * BUFSZ;

        // store W(c) from registers (cvt inline)
        {
            uint32_t o = (uint32_t)(wrow_ld * PADK + wc4_ld) * 2;
            #pragma unroll
            for (int i = 0; i < 4; i++)
                cvt_store(base + OFF_BHI + o + i*16*PADK*2,
                          base + OFF_BLO + o + i*16*PADK*2, wbuf[i]);
        }

        asm volatile("cp.async.wait_group 0;" ::: "memory");
        __syncthreads();   // A(c) + W(c) visible; all warps done with MMA(c-1)

        // issue next chunk's loads (covered by MMA below)
        if (c + 1 < c1) {
            cp_async_A(sb + (uint32_t)((c + 1) & 1) * BUFSZ, Ah, Al, K, m0, (c + 1) << 6, tid);
            ldg_W(wbuf, W, K, n0, (c + 1) << 6, wrow_ld, wc4_ld);
        }

        int kc = K - (c << 6); if (kc > 64) kc = 64;
        int steps = kc >> 4;
        #pragma unroll 4
        for (int s = 0; s < steps; s++) {
            load_frag(f0, base, s << 4, wm, wn, rA, cAo, rB, cBo);
            do_mma(acc, f0);
        }
    }

    // epilogue: raw partial store
    int r0 = lane >> 2, cq = (lane & 3) * 2;
    #pragma unroll
    for (int mi = 0; mi < 2; mi++) {
        #pragma unroll
        for (int ni = 0; ni < 4; ni++) {
            int col = n0 + wn*32 + ni*8 + cq;
            int row = m0 + wm*32 + mi*16 + r0;
            float2 v0 = make_float2(acc[mi][ni][0], acc[mi][ni][1]);
            float2 v1 = make_float2(acc[mi][ni][2], acc[mi][ni][3]);
            *(float2*)(Out + (size_t)row * Hn + col) = v0;
            *(float2*)(Out + (size_t)(row + 8) * Hn + col) = v1;
        }
    }
}

// ------------------------- finalize A: stage0 (fp32 hid) + stage1 (bf16 h1 planes), 2 splits -
__global__ void finalizeA_kernel(
    const float* __restrict__ b_ner, const float* __restrict__ b_emd,
    const float* __restrict__ b_rel, const float* __restrict__ b_cr)
{
    int prob = blockIdx.y;
    int idx4 = (blockIdx.x * 256 + threadIdx.x) * 4;
    if (idx4 < S0_ELEM) {
        const float* p = d_cpart + (size_t)(prob*2) * S0_ELEM + idx4;
        float4 a = *(const float4*)p;
        float4 b = *(const float4*)(p + S0_ELEM);
        float4 bb = *(const float4*)((prob ? b_emd : b_ner) + (idx4 % Hn));
        float4 r;
        r.x = fmaxf(a.x + b.x + bb.x, 0.f);
        r.y = fmaxf(a.y + b.y + bb.y, 0.f);
        r.z = fmaxf(a.z + b.z + bb.z, 0.f);
        r.w = fmaxf(a.w + b.w + bb.w, 0.f);
        *(float4*)((prob ? d_hid_emd : d_hid_ner) + idx4) = r;
    } else {
        int j = idx4 - S0_ELEM;
        if (j >= S1_ELEM) return;
        const float* p = d_cpart + S1_BASE + (size_t)(prob*2) * S1_ELEM + j;
        float4 a = *(const float4*)p;
        float4 b = *(const float4*)(p + S1_ELEM);
        float4 bb = *(const float4*)((prob ? b_cr : b_rel) + (j % Hn));
        float4 r;
        r.x = fmaxf(a.x + b.x + bb.x, 0.f);
        r.y = fmaxf(a.y + b.y + bb.y, 0.f);
        r.z = fmaxf(a.z + b.z + bb.z, 0.f);
        r.w = fmaxf(a.w + b.w + bb.w, 0.f);
        uint2 h, l; cvt_hilo(r, h, l);
        size_t off = (prob ? A_H1_1 : A_H1_0) + j;
        *(uint2*)&d_a_hi[off] = h;
        *(uint2*)&d_a_lo[off] = l;
    }
}

// ------------------------- finalize B: stage2 (sum 2 splits, fp32 h2) -------------------------
__global__ void finalizeB_kernel(
    const float* __restrict__ b_rel, const float* __restrict__ b_cr)
{
    int prob = blockIdx.y;
    int idx4 = (blockIdx.x * 256 + threadIdx.x) * 4;
    if (idx4 >= S1_ELEM) return;
    const float* p = d_cpart + (size_t)(prob*2) * S1_ELEM + idx4;
    float4 a = *(const float4*)p;
    float4 b = *(const float4*)(p + S1_ELEM);
    float4 bb = *(const float4*)((prob ? b_cr : b_rel) + (idx4 % Hn));
    float4 r;
    r.x = fmaxf(a.x + b.x + bb.x, 0.f);
    r.y = fmaxf(a.y + b.y + bb.y, 0.f);
    r.z = fmaxf(a.z + b.z + bb.z, 0.f);
    r.w = fmaxf(a.w + b.w + bb.w, 0.f);
    *(float4*)((prob ? d_h2_cr : d_h2_rel) + idx4) = r;
}

// ------------------------- heads -------------------------
__global__ void heads_kernel(
    const float* __restrict__ ner_hw, const float* __restrict__ ner_hb,
    const float* __restrict__ emd_hw, const float* __restrict__ emd_hb,
    const float* __restrict__ rel_w3, const float* __restrict__ rel_b3,
    const float* __restrict__ cr_w3,  const float* __restrict__ cr_b3,
    float* __restrict__ out)
{
    int gwarp = (blockIdx.x * blockDim.x + threadIdx.x) >> 5;
    int lane = threadIdx.x & 31;
    if (gwarp >= 3840) return;
    const float* A; const float* Wr; float bias;
    if (gwarp < 1280) {
        int r = gwarp / 10, n = gwarp % 10;
        A = d_hid_ner + (size_t)r*Hn; Wr = ner_hw + (size_t)n*Hn; bias = ner_hb[n];
    } else if (gwarp < 3328) {
        int i = gwarp - 1280; int r = i / 8, n = i % 8;
        A = d_h2_rel + (size_t)r*Hn; Wr = rel_w3 + (size_t)n*Hn; bias = rel_b3[n];
    } else if (gwarp < 3584) {
        int i = gwarp - 3328; int r = i / 2, n = i & 1;
        A = d_hid_emd + (size_t)r*Hn; Wr = emd_hw + (size_t)n*Hn; bias = emd_hb[n];
    } else {
        int i = gwarp - 3584;
        A = d_h2_cr + (size_t)i*Hn; Wr = cr_w3; bias = cr_b3[0];
    }
    float s = 0.f;
    for (int k = lane*4; k < Hn; k += 128) {
        float4 a = *(const float4*)(A + k);
        float4 w = *(const float4*)(Wr + k);
        s += a.x*w.x + a.y*w.y + a.z*w.z + a.w*w.w;
    }
    #pragma unroll
    for (int o = 16; o; o >>= 1) s += __shfl_xor_sync(0xffffffffu, s, o);
    if (lane == 0) out[gwarp] = s + bias;
}

// ------------------------- launch -------------------------
extern "C" void kernel_launch(void* const* d_in, const int* in_sizes, int n_in,
                              void* d_out, int out_size)
{
    const int*   input_ids       = (const int*)  d_in[0];
    const int*   entity_masks    = (const int*)  d_in[1];
    const int*   entity_sizes    = (const int*)  d_in[2];
    const int*   mention_masks   = (const int*)  d_in[3];
    const int*   mention_sizes   = (const int*)  d_in[4];
    const int*   relations       = (const int*)  d_in[5];
    const int*   rel_masks       = (const int*)  d_in[6];
    const int*   references      = (const int*)  d_in[7];
    const int*   references_masks= (const int*)  d_in[8];
    const float* emb             = (const float*)d_in[9];
    const float* ner_size_emb    = (const float*)d_in[10];
    const float* emd_size_emb    = (const float*)d_in[11];
    const float* ner_rep_w = (const float*)d_in[12]; const float* ner_rep_b = (const float*)d_in[13];
    const float* ner_head_w= (const float*)d_in[14]; const float* ner_head_b= (const float*)d_in[15];
    const float* emd_rep_w = (const float*)d_in[16]; const float* emd_rep_b = (const float*)d_in[17];
    const float* emd_head_w= (const float*)d_in[18]; const float* emd_head_b= (const float*)d_in[19];
    const float* rel_w1 = (const float*)d_in[20]; const float* rel_b1 = (const float*)d_in[21];
    const float* rel_w2 = (const float*)d_in[22]; const float* rel_b2 = (const float*)d_in[23];
    const float* rel_w3 = (const float*)d_in[24]; const float* rel_b3 = (const float*)d_in[25];
    const float* cr_w1  = (const float*)d_in[26]; const float* cr_b1  = (const float*)d_in[27];
    const float* cr_w2  = (const float*)d_in[28]; const float* cr_b2  = (const float*)d_in[29];
    const float* cr_w3  = (const float*)d_in[30]; const float* cr_b3  = (const float*)d_in[31];
    float* out = (float*)d_out;

    const int smem_bytes = 2 * BUFSZ;   // 110592/CTA
    cudaFuncSetAttribute(gemm_mma_kernel, cudaFuncAttributeMaxDynamicSharedMemorySize, smem_bytes);

    pool_kernel<<<194, 192>>>(entity_masks, mention_masks, rel_masks, references_masks,
                              input_ids, emb);
    assemble_kernel<<<768, 256>>>(entity_sizes, mention_sizes, relations, references,
                                  ner_size_emb, emd_size_emb);

    // launch 1: stage0 split-K2 (48) + stage1 split-K2 (96) = 144 CTAs
    gemm_mma_kernel<<<144, 256, smem_bytes>>>(ner_rep_w, emd_rep_w, rel_w1, cr_w1, 0);
    {
        dim3 f((S0_ELEM + S1_ELEM)/1024, 2);
        finalizeA_kernel<<<f, 256>>>(ner_rep_b, emd_rep_b, rel_b1, cr_b1);
    }

    // launch 2: stage2 split-K2 (96 CTAs)
    gemm_mma_kernel<<<96, 256, smem_bytes>>>(rel_w2, cr_w2, nullptr, nullptr, 1);
    {
        dim3 f(S1_ELEM/1024, 2);
        finalizeB_kernel<<<f, 256>>>(rel_b2, cr_b2);
    }

    heads_kernel<<<480, 256>>>(ner_head_w, ner_head_b, emd_head_w, emd_head_b,
                               rel_w3, rel_b3, cr_w3, cr_b3, out);
}

// round 16
// speedup vs baseline: 1.0844x; 1.0003x over previous
#include <cuda_runtime.h>
#include <cuda_bf16.h>
#include <stdint.h>

#define Bn 2
#define Sn 512
#define Hn 768
#define En 64
#define Mn 64
#define Rn 128
#define SIZE_E 32
#define CLS_ID 101
#define REP_K (2*Hn + SIZE_E)    /* 1568 */
#define REL_K (3*Hn + 2*SIZE_E)  /* 2368 */
#define NEGV (-1e30f)

// activation bf16 plane offsets (elements)
#define A_REP0  0
#define A_REP1  200704
#define A_REPR0 401408
#define A_REPR1 1007616
#define A_H1_0  1613824
#define A_H1_1  1810432
#define A_PLANE 2007040

// ------------------------- device scratch -------------------------
__device__ float d_ctx[Bn*Hn];
__device__ float d_ppool[768*4*Hn];
__device__ int   d_pany[768*4];
__device__ __nv_bfloat16 d_a_hi[A_PLANE];
__device__ __nv_bfloat16 d_a_lo[A_PLANE];
__device__ float d_cpart[2359296];

#define S0_ELEM (128*Hn)       /* 98304  : stage0 regions [0, 4*S0_ELEM) */
#define S1_BASE 786432         /* stage1 regions [S1_BASE, S1_BASE+4*S1_ELEM) */
#define S1_ELEM (256*Hn)       /* 196608 */
#define S2_BASE 1572864        /* stage2 regions (kept distinct from stage0: heads reads both) */

// ------------------------- helpers -------------------------
__device__ __forceinline__ uint32_t smem_u32(const void* p) {
    uint32_t r;
    asm("{ .reg .u64 t; cvta.to.shared.u64 t, %1; cvt.u32.u64 %0, t; }" : "=r"(r) : "l"(p));
    return r;
}
__device__ __forceinline__ void ldsm4(uint32_t addr, uint32_t& r0, uint32_t& r1,
                                      uint32_t& r2, uint32_t& r3) {
    asm volatile("ldmatrix.sync.aligned.m8n8.x4.shared.b16 {%0,%1,%2,%3}, [%4];"
                 : "=r"(r0), "=r"(r1), "=r"(r2), "=r"(r3) : "r"(addr));
}
__device__ __forceinline__ void mma16816(float* d, const uint32_t* a, uint32_t b0, uint32_t b1) {
    asm volatile("mma.sync.aligned.m16n8k16.row.col.f32.bf16.bf16.f32 "
        "{%0,%1,%2,%3}, {%4,%5,%6,%7}, {%8,%9}, {%0,%1,%2,%3};"
        : "+f"(d[0]), "+f"(d[1]), "+f"(d[2]), "+f"(d[3])
        : "r"(a[0]), "r"(a[1]), "r"(a[2]), "r"(a[3]), "r"(b0), "r"(b1));
}
__device__ __forceinline__ void cvt_hilo(float4 v, uint2& h, uint2& l)
{
    __nv_bfloat162 hx = __floats2bfloat162_rn(v.x, v.y);
    __nv_bfloat162 hz = __floats2bfloat162_rn(v.z, v.w);
    float2 fx = __bfloat1622float2(hx);
    float2 fz = __bfloat1622float2(hz);
    __nv_bfloat162 lx = __floats2bfloat162_rn(v.x - fx.x, v.y - fx.y);
    __nv_bfloat162 lz = __floats2bfloat162_rn(v.z - fz.x, v.w - fz.y);
    h.x = *(uint32_t*)&hx; h.y = *(uint32_t*)&hz;
    l.x = *(uint32_t*)&lx; l.y = *(uint32_t*)&lz;
}
__device__ __forceinline__ void cvt_store(uint32_t phi, uint32_t plo, float4 v)
{
    uint2 h, l; cvt_hilo(v, h, l);
    asm volatile("st.shared.v2.b32 [%0], {%1, %2};" :: "r"(phi), "r"(h.x), "r"(h.y) : "memory");
    asm volatile("st.shared.v2.b32 [%0], {%1, %2};" :: "r"(plo), "r"(l.x), "r"(l.y) : "memory");
}
__device__ __forceinline__ float4 pool_max4(int span, int cc)
{
    float4 v = *(const float4*)&d_ppool[((size_t)span*4 + 0)*Hn + cc];
    #pragma unroll
    for (int ch = 1; ch < 4; ch++) {
        float4 p = *(const float4*)&d_ppool[((size_t)span*4 + ch)*Hn + cc];
        v.x = fmaxf(v.x, p.x); v.y = fmaxf(v.y, p.y);
        v.z = fmaxf(v.z, p.z); v.w = fmaxf(v.w, p.w);
    }
    return v;
}

// ------------------------- pooled masked max (+ ctx blocks at end) -------------------------
__global__ __launch_bounds__(192) void pool_kernel(
    const int* __restrict__ em, const int* __restrict__ mm,
    const int* __restrict__ rm, const int* __restrict__ fm,
    const int* __restrict__ input_ids,
    const float* __restrict__ emb)
{
    int blk = blockIdx.x;
    int tid = threadIdx.x;
    if (blk >= 192) {
        int b = blk - 192;
        __shared__ int cidx;
        if (tid == 0) cidx = Sn;
        __syncthreads();
        for (int s = tid; s < Sn; s += blockDim.x)
            if (input_ids[b*Sn + s] == CLS_ID) atomicMin(&cidx, s);
        __syncthreads();
        int ci = (cidx == Sn) ? 0 : cidx;
        for (int h = tid; h < Hn; h += blockDim.x)
            d_ctx[b*Hn + h] = emb[((size_t)b*Sn + ci)*Hn + h];
        return;
    }
    const int* masks; int Kspans, sgbase, local;
    if (blk < 32)       { masks = em; Kspans = En; sgbase = 0;   local = blk; }
    else if (blk < 64)  { masks = mm; Kspans = Mn; sgbase = 128; local = blk - 32; }
    else if (blk < 128) { masks = rm; Kspans = Rn; sgbase = 256; local = blk - 64; }
    else                { masks = fm; Kspans = Rn; sgbase = 512; local = blk - 128; }

    int gpb   = Kspans >> 4;
    int b     = local / (gpb*4);
    int rem   = local % (gpb*4);
    int g     = rem >> 2;
    int chunk = rem & 3;
    int s0    = chunk * 128;
    int k0    = g * 16;
    int sg0   = sgbase + b*Kspans + k0;

    __shared__ unsigned mw[128];
    __shared__ unsigned anyw;
    if (tid < 128) mw[tid] = 0u;
    if (tid == 0) anyw = 0u;
    __syncthreads();

    for (int i = tid; i < 16*128; i += 192) {
        int t = i >> 7, sl = i & 127;
        if (masks[(size_t)(b*Kspans + k0 + t)*Sn + s0 + sl] != 0)
            atomicOr(&mw[sl], 1u << t);
    }
    __syncthreads();

    unsigned aw = 0u;
    for (int sl = tid; sl < 128; sl += 192) aw |= mw[sl];
    if (aw) atomicOr(&anyw, aw);
    __syncthreads();

    int h0 = tid * 4;
    float4 acc[16];
    #pragma unroll
    for (int t = 0; t < 16; t++) acc[t] = make_float4(NEGV, NEGV, NEGV, NEGV);

    const float* ebase = emb + ((size_t)b*Sn + s0)*Hn + h0;
    for (int sl = 0; sl < 128; sl++) {
        float4 v = *(const float4*)(ebase + (size_t)sl*Hn);
        unsigned m = mw[sl];
        #pragma unroll
        for (int t = 0; t < 16; t++) {
            if (m & (1u << t)) {
                acc[t].x = fmaxf(acc[t].x, v.x);
                acc[t].y = fmaxf(acc[t].y, v.y);
                acc[t].z = fmaxf(acc[t].z, v.z);
                acc[t].w = fmaxf(acc[t].w, v.w);
            }
        }
    }
    unsigned a = anyw;
    #pragma unroll
    for (int t = 0; t < 16; t++)
        *(float4*)&d_ppool[((size_t)(sg0 + t)*4 + chunk)*Hn + h0] = acc[t];
    if (tid < 16) d_pany[(sg0 + tid)*4 + chunk] = (a >> tid) & 1u;
}

// ------------------------- assemble (combine fused): write bf16 hi/lo planes ----------------
__global__ void assemble_kernel(
    const int* __restrict__ entity_sizes, const int* __restrict__ mention_sizes,
    const int* __restrict__ relations,    const int* __restrict__ references,
    const float* __restrict__ ner_size_emb, const float* __restrict__ emd_size_emb)
{
    int row = blockIdx.x;
    int tid = threadIdx.x;
    if (row < 256) {
        int prob = row >> 7;
        int r = row & 127;
        int b = r >> 6;
        int span = prob*128 + r;
        int sz = (prob ? mention_sizes : entity_sizes)[r];
        const float* se = (prob ? emd_size_emb : ner_size_emb) + (size_t)sz*SIZE_E;
        size_t off = (prob ? A_REP1 : A_REP0) + (size_t)r*REP_K;
        for (int i = tid; i < REP_K/4; i += 256) {
            int c = i * 4; float4 v;
            if (c < Hn)            v = *(const float4*)(d_ctx + b*Hn + c);
            else if (c < 2*Hn)     v = pool_max4(span, c - Hn);
            else                   v = *(const float4*)(se + c - 2*Hn);
            uint2 h, l; cvt_hilo(v, h, l);
            *(uint2*)&d_a_hi[off + c] = h;
            *(uint2*)&d_a_lo[off + c] = l;
        }
    } else {
        int isrel = (row < 512);
        int r = isrel ? row - 256 : row - 512;
        int b = r >> 7;
        int span_ctx = (isrel ? 256 : 512) + r;
        const int*   idxs  = isrel ? relations : references;
        const int*   szs   = isrel ? entity_sizes : mention_sizes;
        const float* semb  = isrel ? ner_size_emb : emd_size_emb;
        int pbase = isrel ? 0 : 128;
        int e1 = idxs[r*2], e2 = idxs[r*2 + 1];
        int span1 = pbase + b*64 + e1, span2 = pbase + b*64 + e2;
        const float* s1 = semb + (size_t)szs[b*64 + e1]*SIZE_E;
        const float* s2 = semb + (size_t)szs[b*64 + e2]*SIZE_E;
        int any = d_pany[span_ctx*4] | d_pany[span_ctx*4+1]
                | d_pany[span_ctx*4+2] | d_pany[span_ctx*4+3];
        size_t off = (isrel ? A_REPR0 : A_REPR1) + (size_t)r*REL_K;
        for (int i = tid; i < REL_K/4; i += 256) {
            int c = i * 4; float4 v;
            if (c < Hn) {
                v = pool_max4(span_ctx, c);
                if (!any) v = make_float4(0.f, 0.f, 0.f, 0.f);
            }
            else if (c < 2*Hn)            v = pool_max4(span1, c - Hn);
            else if (c < 3*Hn)            v = pool_max4(span2, c - 2*Hn);
            else if (c < 3*Hn + SIZE_E)   v = *(const float4*)(s1 + c - 3*Hn);
            else                          v = *(const float4*)(s2 + c - 3*Hn - SIZE_E);
            uint2 h, l; cvt_hilo(v, h, l);
            *(uint2*)&d_a_hi[off + c] = h;
            *(uint2*)&d_a_lo[off + c] = l;
        }
    }
}

// ------------------------- HMMA GEMM: cp.async A planes + W reg-prefetch -------------------
#define PADK 72
#define OFF_AHI 0
#define OFF_ALO (128*PADK*2)
#define OFF_BHI (2*128*PADK*2)
#define OFF_BLO (OFF_BHI + 64*PADK*2)
#define BUFSZ   (OFF_BLO + 64*PADK*2)   /* 55296 */

struct Frag {
    uint32_t ah[2][4], al[2][4], bh[2][4], bl[2][4];
};

__device__ __forceinline__ void load_frag(Frag& f, uint32_t base, int k0,
                                          int wm, int wn, int rA, int cAo, int rB, int cBo)
{
    #pragma unroll
    for (int mi = 0; mi < 2; mi++) {
        uint32_t oa = (uint32_t)((wm*32 + mi*16 + rA) * PADK + k0 + cAo) * 2;
        ldsm4(base + OFF_AHI + oa, f.ah[mi][0], f.ah[mi][1], f.ah[mi][2], f.ah[mi][3]);
        ldsm4(base + OFF_ALO + oa, f.al[mi][0], f.al[mi][1], f.al[mi][2], f.al[mi][3]);
    }
    #pragma unroll
    for (int bi = 0; bi < 2; bi++) {
        uint32_t ob = (uint32_t)((wn*32 + bi*16 + rB) * PADK + k0 + cBo) * 2;
        ldsm4(base + OFF_BHI + ob, f.bh[bi][0], f.bh[bi][1], f.bh[bi][2], f.bh[bi][3]);
        ldsm4(base + OFF_BLO + ob, f.bl[bi][0], f.bl[bi][1], f.bl[bi][2], f.bl[bi][3]);
    }
}

// three full sweeps: same-accumulator HMMAs separated by 7 independent HMMAs.
__device__ __forceinline__ void do_mma(float acc[2][4][4], const Frag& f)
{
    #pragma unroll
    for (int mi = 0; mi < 2; mi++)
        #pragma unroll
        for (int ni = 0; ni < 4; ni++) {
            int bi = ni >> 1, p = (ni & 1) * 2;
            mma16816(acc[mi][ni], f.ah[mi], f.bh[bi][p], f.bh[bi][p+1]);
        }
    #pragma unroll
    for (int mi = 0; mi < 2; mi++)
        #pragma unroll
        for (int ni = 0; ni < 4; ni++) {
            int bi = ni >> 1, p = (ni & 1) * 2;
            mma16816(acc[mi][ni], f.ah[mi], f.bl[bi][p], f.bl[bi][p+1]);
        }
    #pragma unroll
    for (int mi = 0; mi < 2; mi++)
        #pragma unroll
        for (int ni = 0; ni < 4; ni++) {
            int bi = ni >> 1, p = (ni & 1) * 2;
            mma16816(acc[mi][ni], f.al[mi], f.bh[bi][p], f.bh[bi][p+1]);
        }
}

__device__ __forceinline__ void cp_async_A(
    uint32_t base, const __nv_bfloat16* Ah, const __nv_bfloat16* Al,
    int K, int m0, int kb, int tid)
{
    #pragma unroll
    for (int i = 0; i < 4; i++) {
        int u = tid + (i << 8);
        int arow = u >> 3, c16 = u & 7;
        uint32_t o = (uint32_t)arow * (PADK*2) + c16*16;
        const __nv_bfloat16* ph = Ah + (size_t)(m0 + arow)*K + kb + c16*8;
        const __nv_bfloat16* pl = Al + (size_t)(m0 + arow)*K + kb + c16*8;
        asm volatile("cp.async.ca.shared.global [%0], [%1], 16;"
                     :: "r"(base + OFF_AHI + o), "l"(ph) : "memory");
        asm volatile("cp.async.ca.shared.global [%0], [%1], 16;"
                     :: "r"(base + OFF_ALO + o), "l"(pl) : "memory");
    }
    asm volatile("cp.async.commit_group;" ::: "memory");
}

__device__ __forceinline__ void ldg_W(float4 (&wbuf)[4], const float* W,
                                      int K, int n0, int kb, int wrow, int c4)
{
    int kc = K - kb; if (kc > 64) kc = 64;
    #pragma unroll
    for (int i = 0; i < 4; i++)
        if (c4 < kc)
            wbuf[i] = *(const float4*)(W + (size_t)(n0 + wrow + i*16)*K + kb + c4);
}

__global__ __launch_bounds__(256, 2) void gemm_mma_kernel(
    const float* __restrict__ Wa, const float* __restrict__ Wb,
    const float* __restrict__ Wc, const float* __restrict__ Wd,
    int mode)
{
    extern __shared__ char smem[];
    uint32_t sb = smem_u32(smem);
    int tid = threadIdx.x;
    int wid = tid >> 5, lane = tid & 31;
    int wm = wid & 3, wn = wid >> 2;

    // resolve job (split-K2 everywhere)
    const __nv_bfloat16 *Ah, *Al; const float* W; float* Out;
    int K, m0, n0, c0, c1;
    int bx = blockIdx.x;
    if (mode == 0 && bx < 48) {
        int prob = bx / 24, r = bx % 24, nt = r >> 1, sp = r & 1;
        size_t aoff = prob ? A_REP1 : A_REP0;
        Ah = d_a_hi + aoff; Al = d_a_lo + aoff;
        W = prob ? Wb : Wa;
        Out = d_cpart + (size_t)(prob*2 + sp) * S0_ELEM;
        K = REP_K; m0 = 0; n0 = nt * 64;
        int nc = (K + 63) >> 6;
        c0 = sp * nc / 2; c1 = (sp + 1) * nc / 2;
    } else if (mode == 0) {
        int i = bx - 48;
        int prob = i / 48, r = i % 48;
        int mt = r / 24, r2 = r % 24, nt = r2 >> 1, sp = r2 & 1;
        size_t aoff = prob ? A_REPR1 : A_REPR0;
        Ah = d_a_hi + aoff; Al = d_a_lo + aoff;
        W = prob ? Wd : Wc; K = REL_K;
        Out = d_cpart + S1_BASE + (size_t)(prob*2 + sp) * S1_ELEM;
        m0 = mt * 128; n0 = nt * 64;
        int nc = (K + 63) >> 6;
        c0 = sp * nc / 2; c1 = (sp + 1) * nc / 2;
    } else {
        // stage2 -> S2_BASE (keeps stage0 cpart intact for heads)
        int i = bx;
        int prob = i / 48, r = i % 48;
        int mt = r / 24, r2 = r % 24, nt = r2 >> 1, sp = r2 & 1;
        size_t aoff = prob ? A_H1_1 : A_H1_0;
        Ah = d_a_hi + aoff; Al = d_a_lo + aoff;
        W = prob ? Wb : Wa; K = Hn;
        Out = d_cpart + S2_BASE + (size_t)(prob*2 + sp) * S1_ELEM;
        m0 = mt * 128; n0 = nt * 64;
        c0 = sp * 6; c1 = (sp + 1) * 6;
    }

    int wrow_ld = tid >> 4, wc4_ld = (tid & 15) << 2;

    float acc[2][4][4];
    #pragma unroll
    for (int mi = 0; mi < 2; mi++)
        #pragma unroll
        for (int ni = 0; ni < 4; ni++)
            #pragma unroll
            for (int q = 0; q < 4; q++) acc[mi][ni][q] = 0.f;

    int g = lane >> 3;
    int rA = (lane & 7) + ((g & 1) << 3);
    int cAo = (g & 2) << 2;
    int rB = (lane & 7) + ((g & 2) << 2);
    int cBo = (g & 1) << 3;

    Frag f0;
    float4 wbuf[4];

    ldg_W(wbuf, W, K, n0, c0 << 6, wrow_ld, wc4_ld);
    cp_async_A(sb + (uint32_t)(c0 & 1) * BUFSZ, Ah, Al, K, m0, c0 << 6, tid);

    for (int c = c0; c < c1; c++) {
        uint32_t base = sb + (uint32_t)(c & 1) * BUFSZ;

        {
            uint32_t o = (uint32_t)(wrow_ld * PADK + wc4_ld) * 2;
            #pragma unroll
            for (int i = 0; i < 4; i++)
                cvt_store(base + OFF_BHI + o + i*16*PADK*2,
                          base + OFF_BLO + o + i*16*PADK*2, wbuf[i]);
        }

        asm volatile("cp.async.wait_group 0;" ::: "memory");
        __syncthreads();

        if (c + 1 < c1) {
            cp_async_A(sb + (uint32_t)((c + 1) & 1) * BUFSZ, Ah, Al, K, m0, (c + 1) << 6, tid);
            ldg_W(wbuf, W, K, n0, (c + 1) << 6, wrow_ld, wc4_ld);
        }

        int kc = K - (c << 6); if (kc > 64) kc = 64;
        int steps = kc >> 4;
        #pragma unroll 4
        for (int s = 0; s < steps; s++) {
            load_frag(f0, base, s << 4, wm, wn, rA, cAo, rB, cBo);
            do_mma(acc, f0);
        }
    }

    // epilogue: raw partial store
    int r0 = lane >> 2, cq = (lane & 3) * 2;
    #pragma unroll
    for (int mi = 0; mi < 2; mi++) {
        #pragma unroll
        for (int ni = 0; ni < 4; ni++) {
            int col = n0 + wn*32 + ni*8 + cq;
            int row = m0 + wm*32 + mi*16 + r0;
            float2 v0 = make_float2(acc[mi][ni][0], acc[mi][ni][1]);
            float2 v1 = make_float2(acc[mi][ni][2], acc[mi][ni][3]);
            *(float2*)(Out + (size_t)row * Hn + col) = v0;
            *(float2*)(Out + (size_t)(row + 8) * Hn + col) = v1;
        }
    }
}

// ------------------------- finalize A: stage1 only (bf16 h1 planes) -------------------------
__global__ void finalizeA_kernel(
    const float* __restrict__ b_rel, const float* __restrict__ b_cr)
{
    int prob = blockIdx.y;
    int j = (blockIdx.x * 256 + threadIdx.x) * 4;
    if (j >= S1_ELEM) return;
    const float* p = d_cpart + S1_BASE + (size_t)(prob*2) * S1_ELEM + j;
    float4 a = *(const float4*)p;
    float4 b = *(const float4*)(p + S1_ELEM);
    float4 bb = *(const float4*)((prob ? b_cr : b_rel) + (j % Hn));
    float4 r;
    r.x = fmaxf(a.x + b.x + bb.x, 0.f);
    r.y = fmaxf(a.y + b.y + bb.y, 0.f);
    r.z = fmaxf(a.z + b.z + bb.z, 0.f);
    r.w = fmaxf(a.w + b.w + bb.w, 0.f);
    uint2 h, l; cvt_hilo(r, h, l);
    size_t off = (prob ? A_H1_1 : A_H1_0) + j;
    *(uint2*)&d_a_hi[off] = h;
    *(uint2*)&d_a_lo[off] = l;
}

// ------------------------- heads: fused bias+relu from cpart + dot products -----------------
__global__ void heads_kernel(
    const float* __restrict__ ner_hw, const float* __restrict__ ner_hb,
    const float* __restrict__ emd_hw, const float* __restrict__ emd_hb,
    const float* __restrict__ rel_w3, const float* __restrict__ rel_b3,
    const float* __restrict__ cr_w3,  const float* __restrict__ cr_b3,
    const float* __restrict__ ner_rep_b, const float* __restrict__ emd_rep_b,
    const float* __restrict__ rel_b2,    const float* __restrict__ cr_b2,
    float* __restrict__ out)
{
    int gwarp = (blockIdx.x * blockDim.x + threadIdx.x) >> 5;
    int lane = threadIdx.x & 31;
    if (gwarp >= 3840) return;
    const float* c0; const float* bv; const float* Wr; float bias;
    if (gwarp < 1280) {                  // entity: hid_ner row from stage0 cpart (prob 0)
        int r = gwarp / 10, n = gwarp % 10;
        c0 = d_cpart + (size_t)r*Hn;                 // regions 0 (sp0), +S0_ELEM (sp1)
        bv = ner_rep_b;
        Wr = ner_hw + (size_t)n*Hn; bias = ner_hb[n];
    } else if (gwarp < 3328) {           // rel: h2_rel row from stage2 cpart (prob 0)
        int i = gwarp - 1280; int r = i / 8, n = i % 8;
        c0 = d_cpart + S2_BASE + (size_t)r*Hn;
        bv = rel_b2;
        Wr = rel_w3 + (size_t)n*Hn; bias = rel_b3[n];
    } else if (gwarp < 3584) {           // mention: hid_emd row from stage0 cpart (prob 1)
        int i = gwarp - 3328; int r = i / 2, n = i & 1;
        c0 = d_cpart + 2*(size_t)S0_ELEM + (size_t)r*Hn;
        bv = emd_rep_b;
        Wr = emd_hw + (size_t)n*Hn; bias = emd_hb[n];
    } else {                             // ref: h2_cr row from stage2 cpart (prob 1)
        int i = gwarp - 3584;
        c0 = d_cpart + S2_BASE + 2*(size_t)S1_ELEM + (size_t)i*Hn;
        bv = cr_b2;
        Wr = cr_w3; bias = cr_b3[0];
    }
    int split_stride = (gwarp < 1280) ? S0_ELEM : (gwarp < 3328) ? S1_ELEM
                      : (gwarp < 3584) ? S0_ELEM : S1_ELEM;
    float s = 0.f;
    for (int k = lane*4; k < Hn; k += 128) {
        float4 p0 = *(const float4*)(c0 + k);
        float4 p1 = *(const float4*)(c0 + split_stride + k);
        float4 bb = *(const float4*)(bv + k);
        float4 w  = *(const float4*)(Wr + k);
        float a0 = fmaxf(p0.x + p1.x + bb.x, 0.f);
        float a1 = fmaxf(p0.y + p1.y + bb.y, 0.f);
        float a2 = fmaxf(p0.z + p1.z + bb.z, 0.f);
        float a3 = fmaxf(p0.w + p1.w + bb.w, 0.f);
        s += a0*w.x + a1*w.y + a2*w.z + a3*w.w;
    }
    #pragma unroll
    for (int o = 16; o; o >>= 1) s += __shfl_xor_sync(0xffffffffu, s, o);
    if (lane == 0) out[gwarp] = s + bias;
}

// ------------------------- launch -------------------------
extern "C" void kernel_launch(void* const* d_in, const int* in_sizes, int n_in,
                              void* d_out, int out_size)
{
    const int*   input_ids       = (const int*)  d_in[0];
    const int*   entity_masks    = (const int*)  d_in[1];
    const int*   entity_sizes    = (const int*)  d_in[2];
    const int*   mention_masks   = (const int*)  d_in[3];
    const int*   mention_sizes   = (const int*)  d_in[4];
    const int*   relations       = (const int*)  d_in[5];
    const int*   rel_masks       = (const int*)  d_in[6];
    const int*   references      = (const int*)  d_in[7];
    const int*   references_masks= (const int*)  d_in[8];
    const float* emb             = (const float*)d_in[9];
    const float* ner_size_emb    = (const float*)d_in[10];
    const float* emd_size_emb    = (const float*)d_in[11];
    const float* ner_rep_w = (const float*)d_in[12]; const float* ner_rep_b = (const float*)d_in[13];
    const float* ner_head_w= (const float*)d_in[14]; const float* ner_head_b= (const float*)d_in[15];
    const float* emd_rep_w = (const float*)d_in[16]; const float* emd_rep_b = (const float*)d_in[17];
    const float* emd_head_w= (const float*)d_in[18]; const float* emd_head_b= (const float*)d_in[19];
    const float* rel_w1 = (const float*)d_in[20]; const float* rel_b1 = (const float*)d_in[21];
    const float* rel_w2 = (const float*)d_in[22]; const float* rel_b2 = (const float*)d_in[23];
    const float* rel_w3 = (const float*)d_in[24]; const float* rel_b3 = (const float*)d_in[25];
    const float* cr_w1  = (const float*)d_in[26]; const float* cr_b1  = (const float*)d_in[27];
    const float* cr_w2  = (const float*)d_in[28]; const float* cr_b2  = (const float*)d_in[29];
    const float* cr_w3  = (const float*)d_in[30]; const float* cr_b3  = (const float*)d_in[31];
    float* out = (float*)d_out;

    const int smem_bytes = 2 * BUFSZ;   // 110592/CTA
    cudaFuncSetAttribute(gemm_mma_kernel, cudaFuncAttributeMaxDynamicSharedMemorySize, smem_bytes);

    pool_kernel<<<194, 192>>>(entity_masks, mention_masks, rel_masks, references_masks,
                              input_ids, emb);
    assemble_kernel<<<768, 256>>>(entity_sizes, mention_sizes, relations, references,
                                  ner_size_emb, emd_size_emb);

    // launch 1: stage0 split-K2 (48) + stage1 split-K2 (96) = 144 CTAs
    gemm_mma_kernel<<<144, 256, smem_bytes>>>(ner_rep_w, emd_rep_w, rel_w1, cr_w1, 0);
    {
        dim3 f(S1_ELEM/1024, 2);
        finalizeA_kernel<<<f, 256>>>(rel_b1, cr_b1);
    }

    // launch 2: stage2 split-K2 (96 CTAs) -> S2_BASE
    gemm_mma_kernel<<<96, 256, smem_bytes>>>(rel_w2, cr_w2, nullptr, nullptr, 1);

    // heads: fuses stage0 finalize (ner/emd) and stage2 finalize (rel/cr) inline
    heads_kernel<<<480, 256>>>(ner_head_w, ner_head_b, emd_head_w, emd_head_b,
                               rel_w3, rel_b3, cr_w3, cr_b3,
                               ner_rep_b, emd_rep_b, rel_b2, cr_b2, out);
}

// round 17
// speedup vs baseline: 1.1860x; 1.0937x over previous
#include <cuda_runtime.h>
#include <cuda_bf16.h>
#include <stdint.h>

#define Bn 2
#define Sn 512
#define Hn 768
#define SIZE_E 32
#define CLS_ID 101
#define REP_K 1568
#define REL_K 2368
#define NEGV (-1e30f)

// activation bf16 plane offsets (elements)
#define A_POOLN 0          /* [128 x 832] ner pools+size (cols 800:832 zero) */
#define A_POOLM 106496     /* [128 x 832] emd pools+size */
#define A_CTXR  212992     /* [256 x 768] rel masked ctx */
#define A_CTXC  409600     /* [256 x 768] cr masked ctx */
#define A_H1_0  606208     /* [256 x 768] */
#define A_H1_1  802816
#define A_PLANE 999424

// cpart regions (floats)
#define S0_ELEM 98304      /* 128*768; stage0: [0, 4*S0_ELEM) */
#define CTXB    393216     /* stage1-ctx: 4 x 196608 */
#define S1_ELEM 196608
#define PB      1179648    /* stage1-P: 4 x 196608 (128 x 1536) */
#define S2B     1966080    /* stage2: 4 x 196608 */

__device__ float d_ctx[Bn*Hn];
__device__ float d_ppool[768*4*Hn];
__device__ int   d_pany[768*4];
__device__ float d_yctx[2*2*Hn];
__device__ __nv_bfloat16 d_a_hi[A_PLANE];
__device__ __nv_bfloat16 d_a_lo[A_PLANE];
__device__ float d_cpart[2752512];

// ------------------------- helpers -------------------------
__device__ __forceinline__ uint32_t smem_u32(const void* p) {
    uint32_t r;
    asm("{ .reg .u64 t; cvta.to.shared.u64 t, %1; cvt.u32.u64 %0, t; }" : "=r"(r) : "l"(p));
    return r;
}
__device__ __forceinline__ void ldsm4(uint32_t addr, uint32_t& r0, uint32_t& r1,
                                      uint32_t& r2, uint32_t& r3) {
    asm volatile("ldmatrix.sync.aligned.m8n8.x4.shared.b16 {%0,%1,%2,%3}, [%4];"
                 : "=r"(r0), "=r"(r1), "=r"(r2), "=r"(r3) : "r"(addr));
}
__device__ __forceinline__ void mma16816(float* d, const uint32_t* a, uint32_t b0, uint32_t b1) {
    asm volatile("mma.sync.aligned.m16n8k16.row.col.f32.bf16.bf16.f32 "
        "{%0,%1,%2,%3}, {%4,%5,%6,%7}, {%8,%9}, {%0,%1,%2,%3};"
        : "+f"(d[0]), "+f"(d[1]), "+f"(d[2]), "+f"(d[3])
        : "r"(a[0]), "r"(a[1]), "r"(a[2]), "r"(a[3]), "r"(b0), "r"(b1));
}
__device__ __forceinline__ void cvt_hilo(float4 v, uint2& h, uint2& l)
{
    __nv_bfloat162 hx = __floats2bfloat162_rn(v.x, v.y);
    __nv_bfloat162 hz = __floats2bfloat162_rn(v.z, v.w);
    float2 fx = __bfloat1622float2(hx);
    float2 fz = __bfloat1622float2(hz);
    __nv_bfloat162 lx = __floats2bfloat162_rn(v.x - fx.x, v.y - fx.y);
    __nv_bfloat162 lz = __floats2bfloat162_rn(v.z - fz.x, v.w - fz.y);
    h.x = *(uint32_t*)&hx; h.y = *(uint32_t*)&hz;
    l.x = *(uint32_t*)&lx; l.y = *(uint32_t*)&lz;
}
__device__ __forceinline__ void cvt_store(uint32_t phi, uint32_t plo, float4 v)
{
    uint2 h, l; cvt_hilo(v, h, l);
    asm volatile("st.shared.v2.b32 [%0], {%1, %2};" :: "r"(phi), "r"(h.x), "r"(h.y) : "memory");
    asm volatile("st.shared.v2.b32 [%0], {%1, %2};" :: "r"(plo), "r"(l.x), "r"(l.y) : "memory");
}
__device__ __forceinline__ float4 pool_max4(int span, int cc)
{
    float4 v = *(const float4*)&d_ppool[((size_t)span*4 + 0)*Hn + cc];
    #pragma unroll
    for (int ch = 1; ch < 4; ch++) {
        float4 p = *(const float4*)&d_ppool[((size_t)span*4 + ch)*Hn + cc];
        v.x = fmaxf(v.x, p.x); v.y = fmaxf(v.y, p.y);
        v.z = fmaxf(v.z, p.z); v.w = fmaxf(v.w, p.w);
    }
    return v;
}

// ------------------------- pooled masked max (+ ctx blocks) -------------------------
__global__ __launch_bounds__(192) void pool_kernel(
    const int* __restrict__ em, const int* __restrict__ mm,
    const int* __restrict__ rm, const int* __restrict__ fm,
    const int* __restrict__ input_ids,
    const float* __restrict__ emb)
{
    int blk = blockIdx.x;
    int tid = threadIdx.x;
    if (blk >= 192) {
        int b = blk - 192;
        __shared__ int cidx;
        if (tid == 0) cidx = Sn;
        __syncthreads();
        for (int s = tid; s < Sn; s += blockDim.x)
            if (input_ids[b*Sn + s] == CLS_ID) atomicMin(&cidx, s);
        __syncthreads();
        int ci = (cidx == Sn) ? 0 : cidx;
        for (int h = tid; h < Hn; h += blockDim.x)
            d_ctx[b*Hn + h] = emb[((size_t)b*Sn + ci)*Hn + h];
        return;
    }
    const int* masks; int Kspans, sgbase, local;
    if (blk < 32)       { masks = em; Kspans = 64;  sgbase = 0;   local = blk; }
    else if (blk < 64)  { masks = mm; Kspans = 64;  sgbase = 128; local = blk - 32; }
    else if (blk < 128) { masks = rm; Kspans = 128; sgbase = 256; local = blk - 64; }
    else                { masks = fm; Kspans = 128; sgbase = 512; local = blk - 128; }

    int gpb   = Kspans >> 4;
    int b     = local / (gpb*4);
    int rem   = local % (gpb*4);
    int g     = rem >> 2;
    int chunk = rem & 3;
    int s0    = chunk * 128;
    int k0    = g * 16;
    int sg0   = sgbase + b*Kspans + k0;

    __shared__ unsigned mw[128];
    __shared__ unsigned anyw;
    if (tid < 128) mw[tid] = 0u;
    if (tid == 0) anyw = 0u;
    __syncthreads();

    for (int i = tid; i < 16*128; i += 192) {
        int t = i >> 7, sl = i & 127;
        if (masks[(size_t)(b*Kspans + k0 + t)*Sn + s0 + sl] != 0)
            atomicOr(&mw[sl], 1u << t);
    }
    __syncthreads();

    unsigned aw = 0u;
    for (int sl = tid; sl < 128; sl += 192) aw |= mw[sl];
    if (aw) atomicOr(&anyw, aw);
    __syncthreads();

    int h0 = tid * 4;
    float4 acc[16];
    #pragma unroll
    for (int t = 0; t < 16; t++) acc[t] = make_float4(NEGV, NEGV, NEGV, NEGV);

    const float* ebase = emb + ((size_t)b*Sn + s0)*Hn + h0;
    for (int sl = 0; sl < 128; sl++) {
        float4 v = *(const float4*)(ebase + (size_t)sl*Hn);
        unsigned m = mw[sl];
        #pragma unroll
        for (int t = 0; t < 16; t++) {
            if (m & (1u << t)) {
                acc[t].x = fmaxf(acc[t].x, v.x);
                acc[t].y = fmaxf(acc[t].y, v.y);
                acc[t].z = fmaxf(acc[t].z, v.z);
                acc[t].w = fmaxf(acc[t].w, v.w);
            }
        }
    }
    unsigned a = anyw;
    #pragma unroll
    for (int t = 0; t < 16; t++)
        *(float4*)&d_ppool[((size_t)(sg0 + t)*4 + chunk)*Hn + h0] = acc[t];
    if (tid < 16) d_pany[(sg0 + tid)*4 + chunk] = (a >> tid) & 1u;
}

// ------------------------- assemble: pools/ctx planes + y_ctx GEMV -------------------------
// grid 1152: [0,256) pools rows, [256,768) masked-ctx rows, [768,1152) y_ctx warps
__global__ void assemble_kernel(
    const int* __restrict__ entity_sizes, const int* __restrict__ mention_sizes,
    const float* __restrict__ ner_size_emb, const float* __restrict__ emd_size_emb,
    const float* __restrict__ ner_rep_w,   const float* __restrict__ emd_rep_w)
{
    int row = blockIdx.x;
    int tid = threadIdx.x;
    if (row < 256) {
        // pools plane: [pool(768) | size(32) | zeros(32)] row-stride 832
        int prob = row >> 7;        // 0=ner(entity), 1=emd(mention)
        int r = row & 127;
        int span = prob*128 + r;
        int sz = (prob ? mention_sizes : entity_sizes)[r];
        const float* se = (prob ? emd_size_emb : ner_size_emb) + (size_t)sz*SIZE_E;
        size_t off = (prob ? A_POOLM : A_POOLN) + (size_t)r*832;
        for (int i = tid; i < 208; i += 256) {
            int c = i * 4; float4 v;
            if (c < 768)       v = pool_max4(span, c);
            else if (c < 800)  v = *(const float4*)(se + c - 768);
            else               v = make_float4(0.f, 0.f, 0.f, 0.f);
            uint2 h, l; cvt_hilo(v, h, l);
            *(uint2*)&d_a_hi[off + c] = h;
            *(uint2*)&d_a_lo[off + c] = l;
        }
    } else if (row < 768) {
        int isrel = (row < 512);
        int r = isrel ? row - 256 : row - 512;
        int span_ctx = (isrel ? 256 : 512) + r;
        int any = d_pany[span_ctx*4] | d_pany[span_ctx*4+1]
                | d_pany[span_ctx*4+2] | d_pany[span_ctx*4+3];
        size_t off = (isrel ? A_CTXR : A_CTXC) + (size_t)r*768;
        for (int i = tid; i < 192; i += 256) {
            int c = i * 4;
            float4 v = pool_max4(span_ctx, c);
            if (!any) v = make_float4(0.f, 0.f, 0.f, 0.f);
            uint2 h, l; cvt_hilo(v, h, l);
            *(uint2*)&d_a_hi[off + c] = h;
            *(uint2*)&d_a_lo[off + c] = l;
        }
    } else {
        // y_ctx GEMV: 3072 outputs = (prob, b, n); warp per output, fp32 exact
        int gwarp = (row - 768) * 8 + (tid >> 5);
        int lane = tid & 31;
        int prob = gwarp / 1536, rem = gwarp % 1536;
        int b = rem / 768, n = rem % 768;
        const float* W = (prob ? emd_rep_w : ner_rep_w) + (size_t)n * REP_K;
        const float* cx = d_ctx + b * Hn;
        float s = 0.f;
        for (int k = lane*4; k < 768; k += 128) {
            float4 a = *(const float4*)(cx + k);
            float4 w = *(const float4*)(W + k);
            s += a.x*w.x + a.y*w.y + a.z*w.z + a.w*w.w;
        }
        #pragma unroll
        for (int o = 16; o; o >>= 1) s += __shfl_xor_sync(0xffffffffu, s, o);
        if (lane == 0) d_yctx[(prob*2 + b)*Hn + n] = s;
    }
}

// ------------------------- HMMA GEMM -------------------------
#define PADK 72
#define OFF_AHI 0
#define OFF_ALO (128*PADK*2)
#define OFF_BHI (2*128*PADK*2)
#define OFF_BLO (OFF_BHI + 64*PADK*2)
#define BUFSZ   (OFF_BLO + 64*PADK*2)   /* 55296 */

struct Frag { uint32_t ah[2][4], al[2][4], bh[2][4], bl[2][4]; };

__device__ __forceinline__ void load_frag(Frag& f, uint32_t base, int k0,
                                          int wm, int wn, int rA, int cAo, int rB, int cBo)
{
    #pragma unroll
    for (int mi = 0; mi < 2; mi++) {
        uint32_t oa = (uint32_t)((wm*32 + mi*16 + rA) * PADK + k0 + cAo) * 2;
        ldsm4(base + OFF_AHI + oa, f.ah[mi][0], f.ah[mi][1], f.ah[mi][2], f.ah[mi][3]);
        ldsm4(base + OFF_ALO + oa, f.al[mi][0], f.al[mi][1], f.al[mi][2], f.al[mi][3]);
    }
    #pragma unroll
    for (int bi = 0; bi < 2; bi++) {
        uint32_t ob = (uint32_t)((wn*32 + bi*16 + rB) * PADK + k0 + cBo) * 2;
        ldsm4(base + OFF_BHI + ob, f.bh[bi][0], f.bh[bi][1], f.bh[bi][2], f.bh[bi][3]);
        ldsm4(base + OFF_BLO + ob, f.bl[bi][0], f.bl[bi][1], f.bl[bi][2], f.bl[bi][3]);
    }
}

__device__ __forceinline__ void do_mma(float acc[2][4][4], const Frag& f)
{
    #pragma unroll
    for (int mi = 0; mi < 2; mi++)
        #pragma unroll
        for (int ni = 0; ni < 4; ni++) {
            int bi = ni >> 1, p = (ni & 1) * 2;
            mma16816(acc[mi][ni], f.ah[mi], f.bh[bi][p], f.bh[bi][p+1]);
        }
    #pragma unroll
    for (int mi = 0; mi < 2; mi++)
        #pragma unroll
        for (int ni = 0; ni < 4; ni++) {
            int bi = ni >> 1, p = (ni & 1) * 2;
            mma16816(acc[mi][ni], f.ah[mi], f.bl[bi][p], f.bl[bi][p+1]);
        }
    #pragma unroll
    for (int mi = 0; mi < 2; mi++)
        #pragma unroll
        for (int ni = 0; ni < 4; ni++) {
            int bi = ni >> 1, p = (ni & 1) * 2;
            mma16816(acc[mi][ni], f.al[mi], f.bh[bi][p], f.bh[bi][p+1]);
        }
}

__device__ __forceinline__ void cp_async_A(
    uint32_t base, const __nv_bfloat16* Ah, const __nv_bfloat16* Al,
    int Astride, int m0, int kb, int tid)
{
    #pragma unroll
    for (int i = 0; i < 4; i++) {
        int u = tid + (i << 8);
        int arow = u >> 3, c16 = u & 7;
        uint32_t o = (uint32_t)arow * (PADK*2) + c16*16;
        const __nv_bfloat16* ph = Ah + (size_t)(m0 + arow)*Astride + kb + c16*8;
        const __nv_bfloat16* pl = Al + (size_t)(m0 + arow)*Astride + kb + c16*8;
        asm volatile("cp.async.ca.shared.global [%0], [%1], 16;"
                     :: "r"(base + OFF_AHI + o), "l"(ph) : "memory");
        asm volatile("cp.async.ca.shared.global [%0], [%1], 16;"
                     :: "r"(base + OFF_ALO + o), "l"(pl) : "memory");
    }
    asm volatile("cp.async.commit_group;" ::: "memory");
}

__device__ __forceinline__ void ldg_W(float4 (&wbuf)[4], const float* W, int Wld,
                                      int wrowb, int wkb, int kc, int wrow, int c4)
{
    #pragma unroll
    for (int i = 0; i < 4; i++)
        if (c4 < kc)
            wbuf[i] = *(const float4*)(W + (size_t)(wrowb + wrow + i*16)*Wld + wkb + c4);
}

__global__ __launch_bounds__(256, 2) void gemm_mma_kernel(
    const float* __restrict__ Wa, const float* __restrict__ Wb,
    const float* __restrict__ Wc, const float* __restrict__ Wd,
    int mode)
{
    extern __shared__ char smem[];
    uint32_t sb = smem_u32(smem);
    int tid = threadIdx.x;
    int wid = tid >> 5, lane = tid & 31;
    int wm = wid & 3, wn = wid >> 2;

    // job decode
    size_t aoff; int Astride, m0, n0, Kreal, Wld, wrowb, wcolA, wcolB, ostride;
    const float* W; float* Out;
    int bx = blockIdx.x;
    if (mode == 0 && bx < 48) {                 // J0: stage0 pools GEMM
        int prob = bx/24, r = bx%24, nt = r>>1, sp = r&1;
        aoff = prob ? A_POOLM : A_POOLN; Astride = 832; m0 = 0;
        Kreal = 800; W = prob ? Wb : Wa; Wld = REP_K;
        n0 = nt*64; wrowb = n0; wcolA = 768; wcolB = 1536;
        Out = d_cpart + (size_t)(prob*2 + sp)*S0_ELEM; ostride = 768;
        int nc = 13; int c0_ = sp*nc/2, c1_ = (sp+1)*nc/2;
        m0 = (c0_ << 16) | c1_ | (m0 & 0);      // pack trick avoided; fallthrough below
        // (unpack below)
        { int c0 = c0_, c1 = c1_;  // inline main body via goto-free: store in shared? simpler: proceed
          // --- main body (duplicated pattern avoided by falling through with locals) ---
          goto BODY_SETUP;
          BODY_SETUP:;
          // re-declare consistent names
          run:
          {
            const __nv_bfloat16* Ah = d_a_hi + aoff;
            const __nv_bfloat16* Al = d_a_lo + aoff;
            int wrow_ld = tid >> 4, wc4_ld = (tid & 15) << 2;
            float acc[2][4][4];
            #pragma unroll
            for (int mi = 0; mi < 2; mi++)
                #pragma unroll
                for (int ni = 0; ni < 4; ni++)
                    #pragma unroll
                    for (int q = 0; q < 4; q++) acc[mi][ni][q] = 0.f;
            int g = lane >> 3;
            int rA = (lane & 7) + ((g & 1) << 3);
            int cAo = (g & 2) << 2;
            int rB = (lane & 7) + ((g & 2) << 2);
            int cBo = (g & 1) << 3;
            Frag f0; float4 wbuf[4];
            {
                int kb = c0 << 6;
                int kc = Kreal - kb; if (kc > 64) kc = 64;
                int wkb = (kb < 768) ? wcolA + kb : wcolB + (kb - 768);
                ldg_W(wbuf, W, Wld, wrowb, wkb, kc, wrow_ld, wc4_ld);
                cp_async_A(sb + (uint32_t)(c0 & 1)*BUFSZ, Ah, Al, Astride, 0, kb, tid);
            }
            for (int c = c0; c < c1; c++) {
                uint32_t base = sb + (uint32_t)(c & 1)*BUFSZ;
                {
                    uint32_t o = (uint32_t)(wrow_ld * PADK + wc4_ld) * 2;
                    #pragma unroll
                    for (int i = 0; i < 4; i++)
                        cvt_store(base + OFF_BHI + o + i*16*PADK*2,
                                  base + OFF_BLO + o + i*16*PADK*2, wbuf[i]);
                }
                asm volatile("cp.async.wait_group 0;" ::: "memory");
                __syncthreads();
                if (c + 1 < c1) {
                    int kb2 = (c + 1) << 6;
                    int kc2 = Kreal - kb2; if (kc2 > 64) kc2 = 64;
                    int wkb2 = (kb2 < 768) ? wcolA + kb2 : wcolB + (kb2 - 768);
                    cp_async_A(sb + (uint32_t)((c + 1) & 1)*BUFSZ, Ah, Al, Astride, 0, kb2, tid);
                    ldg_W(wbuf, W, Wld, wrowb, wkb2, kc2, wrow_ld, wc4_ld);
                }
                int kc = Kreal - (c << 6); if (kc > 64) kc = 64;
                int steps = kc >> 4;
                #pragma unroll 4
                for (int s = 0; s < steps; s++) {
                    load_frag(f0, base, s << 4, wm, wn, rA, cAo, rB, cBo);
                    do_mma(acc, f0);
                }
            }
            int r0 = lane >> 2, cq = (lane & 3) * 2;
            #pragma unroll
            for (int mi = 0; mi < 2; mi++) {
                #pragma unroll
                for (int ni = 0; ni < 4; ni++) {
                    int col = n0 + wn*32 + ni*8 + cq;
                    int rowo = wm*32 + mi*16 + r0;
                    float2 v0 = make_float2(acc[mi][ni][0], acc[mi][ni][1]);
                    float2 v1 = make_float2(acc[mi][ni][2], acc[mi][ni][3]);
                    *(float2*)(Out + (size_t)rowo * ostride + col) = v0;
                    *(float2*)(Out + (size_t)(rowo + 8) * ostride + col) = v1;
                }
            }
            return;
          }
        }
    }
    // other jobs share one body with explicit parameters
    {
        int c0, c1;
        if (mode == 0 && bx < 144) {            // J1ctx
            int i = bx - 48;
            int prob = i/48, r = i%48;
            int mt = r/24, r2 = r%24, nt = r2>>1, sp = r2&1;
            aoff = (prob ? A_CTXC : A_CTXR) + (size_t)mt*128*768; Astride = 768;
            Kreal = 768; W = prob ? Wd : Wc; Wld = REL_K;
            n0 = nt*64; wrowb = n0; wcolA = 0; wcolB = 0;
            Out = d_cpart + CTXB + (size_t)(prob*2 + sp)*S1_ELEM + (size_t)mt*128*768;
            ostride = 768;
            c0 = sp*6; c1 = (sp+1)*6;
        } else if (mode == 0) {                 // J1P
            int i = bx - 144;
            int prob = i/48, r = i%48, nt = r>>1, sp = r&1;
            aoff = prob ? A_POOLM : A_POOLN; Astride = 832;
            Kreal = 800; W = prob ? Wd : Wc; Wld = REL_K;
            n0 = nt*64;
            if (nt < 12) { wrowb = n0;       wcolA = 768;  wcolB = 2304; }
            else         { wrowb = n0 - 768; wcolA = 1536; wcolB = 2336; }
            Out = d_cpart + PB + (size_t)(prob*2 + sp)*S1_ELEM; ostride = 1536;
            c0 = sp*13/2; c1 = (sp+1)*13/2;
        } else {                                // stage2
            int prob = bx/48, r = bx%48;
            int mt = r/24, r2 = r%24, nt = r2>>1, sp = r2&1;
            aoff = (prob ? A_H1_1 : A_H1_0) + (size_t)mt*128*768; Astride = 768;
            Kreal = 768; W = prob ? Wb : Wa; Wld = 768;
            n0 = nt*64; wrowb = n0; wcolA = 0; wcolB = 0;
            Out = d_cpart + S2B + (size_t)(prob*2 + sp)*S1_ELEM + (size_t)mt*128*768;
            ostride = 768;
            c0 = sp*6; c1 = (sp+1)*6;
        }
        const __nv_bfloat16* Ah = d_a_hi + aoff;
        const __nv_bfloat16* Al = d_a_lo + aoff;
        int wrow_ld = tid >> 4, wc4_ld = (tid & 15) << 2;
        float acc[2][4][4];
        #pragma unroll
        for (int mi = 0; mi < 2; mi++)
            #pragma unroll
            for (int ni = 0; ni < 4; ni++)
                #pragma unroll
                for (int q = 0; q < 4; q++) acc[mi][ni][q] = 0.f;
        int g = lane >> 3;
        int rA = (lane & 7) + ((g & 1) << 3);
        int cAo = (g & 2) << 2;
        int rB = (lane & 7) + ((g & 2) << 2);
        int cBo = (g & 1) << 3;
        Frag f0; float4 wbuf[4];
        {
            int kb = c0 << 6;
            int kc = Kreal - kb; if (kc > 64) kc = 64;
            int wkb = (kb < 768) ? wcolA + kb : wcolB + (kb - 768);
            ldg_W(wbuf, W, Wld, wrowb, wkb, kc, wrow_ld, wc4_ld);
            cp_async_A(sb + (uint32_t)(c0 & 1)*BUFSZ, Ah, Al, Astride, 0, kb, tid);
        }
        for (int c = c0; c < c1; c++) {
            uint32_t base = sb + (uint32_t)(c & 1)*BUFSZ;
            {
                uint32_t o = (uint32_t)(wrow_ld * PADK + wc4_ld) * 2;
                #pragma unroll
                for (int i = 0; i < 4; i++)
                    cvt_store(base + OFF_BHI + o + i*16*PADK*2,
                              base + OFF_BLO + o + i*16*PADK*2, wbuf[i]);
            }
            asm volatile("cp.async.wait_group 0;" ::: "memory");
            __syncthreads();
            if (c + 1 < c1) {
                int kb2 = (c + 1) << 6;
                int kc2 = Kreal - kb2; if (kc2 > 64) kc2 = 64;
                int wkb2 = (kb2 < 768) ? wcolA + kb2 : wcolB + (kb2 - 768);
                cp_async_A(sb + (uint32_t)((c + 1) & 1)*BUFSZ, Ah, Al, Astride, 0, kb2, tid);
                ldg_W(wbuf, W, Wld, wrowb, wkb2, kc2, wrow_ld, wc4_ld);
            }
            int kc = Kreal - (c << 6); if (kc > 64) kc = 64;
            int steps = kc >> 4;
            #pragma unroll 4
            for (int s = 0; s < steps; s++) {
                load_frag(f0, base, s << 4, wm, wn, rA, cAo, rB, cBo);
                do_mma(acc, f0);
            }
        }
        int r0 = lane >> 2, cq = (lane & 3) * 2;
        #pragma unroll
        for (int mi = 0; mi < 2; mi++) {
            #pragma unroll
            for (int ni = 0; ni < 4; ni++) {
                int col = n0 + wn*32 + ni*8 + cq;
                int rowo = wm*32 + mi*16 + r0;
                float2 v0 = make_float2(acc[mi][ni][0], acc[mi][ni][1]);
                float2 v1 = make_float2(acc[mi][ni][2], acc[mi][ni][3]);
                *(float2*)(Out + (size_t)rowo * ostride + col) = v0;
                *(float2*)(Out + (size_t)(rowo + 8) * ostride + col) = v1;
            }
        }
    }
}

// ------------------------- finalize h1: gather ctx + P[e1] + P[e2] + bias, relu, bf16 planes
__global__ void finalizeH1_kernel(
    const int* __restrict__ relations, const int* __restrict__ references,
    const float* __restrict__ rel_b1,  const float* __restrict__ cr_b1)
{
    int prob = blockIdx.y;
    int r = blockIdx.x;           // 0..255
    int n4 = threadIdx.x * 4;     // 192 threads x 4 = 768
    const int* idx = prob ? references : relations;
    int e1 = idx[r*2], e2 = idx[r*2 + 1];
    int b = r >> 7;
    int row1 = b*64 + e1, row2 = b*64 + e2;

    const float* cbase = d_cpart + CTXB + (size_t)(prob*2)*S1_ELEM + (size_t)r*768 + n4;
    const float* pbase = d_cpart + PB + (size_t)(prob*2)*S1_ELEM;
    float4 a0 = *(const float4*)cbase;
    float4 a1 = *(const float4*)(cbase + S1_ELEM);
    float4 p10 = *(const float4*)(pbase + (size_t)row1*1536 + n4);
    float4 p11 = *(const float4*)(pbase + S1_ELEM + (size_t)row1*1536 + n4);
    float4 p20 = *(const float4*)(pbase + (size_t)row2*1536 + 768 + n4);
    float4 p21 = *(const float4*)(pbase + S1_ELEM + (size_t)row2*1536 + 768 + n4);
    float4 bb = *(const float4*)((prob ? cr_b1 : rel_b1) + n4);
    float4 v;
    v.x = fmaxf((a0.x + a1.x) + (p10.x + p11.x) + (p20.x + p21.x) + bb.x, 0.f);
    v.y = fmaxf((a0.y + a1.y) + (p10.y + p11.y) + (p20.y + p21.y) + bb.y, 0.f);
    v.z = fmaxf((a0.z + a1.z) + (p10.z + p11.z) + (p20.z + p21.z) + bb.z, 0.f);
    v.w = fmaxf((a0.w + a1.w) + (p10.w + p11.w) + (p20.w + p21.w) + bb.w, 0.f);
    uint2 h, l; cvt_hilo(v, h, l);
    size_t off = (prob ? A_H1_1 : A_H1_0) + (size_t)r*768 + n4;
    *(uint2*)&d_a_hi[off] = h;
    *(uint2*)&d_a_lo[off] = l;
}

// ------------------------- heads -------------------------
__global__ void heads_kernel(
    const float* __restrict__ ner_hw, const float* __restrict__ ner_hb,
    const float* __restrict__ emd_hw, const float* __restrict__ emd_hb,
    const float* __restrict__ rel_w3, const float* __restrict__ rel_b3,
    const float* __restrict__ cr_w3,  const float* __restrict__ cr_b3,
    const float* __restrict__ ner_rep_b, const float* __restrict__ emd_rep_b,
    const float* __restrict__ rel_b2,    const float* __restrict__ cr_b2,
    float* __restrict__ out)
{
    int gwarp = (blockIdx.x * blockDim.x + threadIdx.x) >> 5;
    int lane = threadIdx.x & 31;
    if (gwarp >= 3840) return;
    const float* c0; const float* bv; const float* Wr; const float* yv = nullptr;
    float bias; int split_stride;
    if (gwarp < 1280) {                  // entity (stage0 prob0)
        int r = gwarp / 10, n = gwarp % 10;
        c0 = d_cpart + (size_t)r*768;
        split_stride = S0_ELEM;
        yv = d_yctx + (size_t)(0*2 + (r>>6))*Hn;
        bv = ner_rep_b;
        Wr = ner_hw + (size_t)n*Hn; bias = ner_hb[n];
    } else if (gwarp < 3328) {           // rel (stage2 prob0)
        int i = gwarp - 1280; int r = i / 8, n = i % 8;
        c0 = d_cpart + S2B + (size_t)r*768;
        split_stride = S1_ELEM;
        bv = rel_b2;
        Wr = rel_w3 + (size_t)n*Hn; bias = rel_b3[n];
    } else if (gwarp < 3584) {           // mention (stage0 prob1)
        int i = gwarp - 3328; int r = i / 2, n = i & 1;
        c0 = d_cpart + 2*(size_t)S0_ELEM + (size_t)r*768;
        split_stride = S0_ELEM;
        yv = d_yctx + (size_t)(1*2 + (r>>6))*Hn;
        bv = emd_rep_b;
        Wr = emd_hw + (size_t)n*Hn; bias = emd_hb[n];
    } else {                             // ref (stage2 prob1)
        int i = gwarp - 3584;
        c0 = d_cpart + S2B + 2*(size_t)S1_ELEM + (size_t)i*768;
        split_stride = S1_ELEM;
        bv = cr_b2;
        Wr = cr_w3; bias = cr_b3[0];
    }
    float s = 0.f;
    for (int k = lane*4; k < Hn; k += 128) {
        float4 p0 = *(const float4*)(c0 + k);
        float4 p1 = *(const float4*)(c0 + split_stride + k);
        float4 bb = *(const float4*)(bv + k);
        float4 w  = *(const float4*)(Wr + k);
        float y0 = 0.f, y1 = 0.f, y2 = 0.f, y3 = 0.f;
        if (yv) { float4 y = *(const float4*)(yv + k); y0 = y.x; y1 = y.y; y2 = y.z; y3 = y.w; }
        float a0 = fmaxf(p0.x + p1.x + y0 + bb.x, 0.f);
        float a1 = fmaxf(p0.y + p1.y + y1 + bb.y, 0.f);
        float a2 = fmaxf(p0.z + p1.z + y2 + bb.z, 0.f);
        float a3 = fmaxf(p0.w + p1.w + y3 + bb.w, 0.f);
        s += a0*w.x + a1*w.y + a2*w.z + a3*w.w;
    }
    #pragma unroll
    for (int o = 16; o; o >>= 1) s += __shfl_xor_sync(0xffffffffu, s, o);
    if (lane == 0) out[gwarp] = s + bias;
}

// ------------------------- launch -------------------------
extern "C" void kernel_launch(void* const* d_in, const int* in_sizes, int n_in,
                              void* d_out, int out_size)
{
    const int*   input_ids       = (const int*)  d_in[0];
    const int*   entity_masks    = (const int*)  d_in[1];
    const int*   entity_sizes    = (const int*)  d_in[2];
    const int*   mention_masks   = (const int*)  d_in[3];
    const int*   mention_sizes   = (const int*)  d_in[4];
    const int*   relations       = (const int*)  d_in[5];
    const int*   rel_masks       = (const int*)  d_in[6];
    const int*   references      = (const int*)  d_in[7];
    const int*   references_masks= (const int*)  d_in[8];
    const float* emb             = (const float*)d_in[9];
    const float* ner_size_emb    = (const float*)d_in[10];
    const float* emd_size_emb    = (const float*)d_in[11];
    const float* ner_rep_w = (const float*)d_in[12]; const float* ner_rep_b = (const float*)d_in[13];
    const float* ner_head_w= (const float*)d_in[14]; const float* ner_head_b= (const float*)d_in[15];
    const float* emd_rep_w = (const float*)d_in[16]; const float* emd_rep_b = (const float*)d_in[17];
    const float* emd_head_w= (const float*)d_in[18]; const float* emd_head_b= (const float*)d_in[19];
    const float* rel_w1 = (const float*)d_in[20]; const float* rel_b1 = (const float*)d_in[21];
    const float* rel_w2 = (const float*)d_in[22]; const float* rel_b2 = (const float*)d_in[23];
    const float* rel_w3 = (const float*)d_in[24]; const float* rel_b3 = (const float*)d_in[25];
    const float* cr_w1  = (const float*)d_in[26]; const float* cr_b1  = (const float*)d_in[27];
    const float* cr_w2  = (const float*)d_in[28]; const float* cr_b2  = (const float*)d_in[29];
    const float* cr_w3  = (const float*)d_in[30]; const float* cr_b3  = (const float*)d_in[31];
    float* out = (float*)d_out;

    const int smem_bytes = 2 * BUFSZ;
    cudaFuncSetAttribute(gemm_mma_kernel, cudaFuncAttributeMaxDynamicSharedMemorySize, smem_bytes);

    pool_kernel<<<194, 192>>>(entity_masks, mention_masks, rel_masks, references_masks,
                              input_ids, emb);
    assemble_kernel<<<1152, 256>>>(entity_sizes, mention_sizes,
                                   ner_size_emb, emd_size_emb, ner_rep_w, emd_rep_w);

    // launch 1: J0 (48) + J1ctx (96) + J1P (96) = 240 CTAs
    gemm_mma_kernel<<<240, 256, smem_bytes>>>(ner_rep_w, emd_rep_w, rel_w1, cr_w1, 0);
    {
        dim3 f(256, 2);
        finalizeH1_kernel<<<f, 192>>>(relations, references, rel_b1, cr_b1);
    }

    // launch 2: stage2 (96 CTAs)
    gemm_mma_kernel<<<96, 256, smem_bytes>>>(rel_w2, cr_w2, nullptr, nullptr, 1);

    heads_kernel<<<480, 256>>>(ner_head_w, ner_head_b, emd_head_w, emd_head_b,
                               rel_w3, rel_b3, cr_w3, cr_b3,
                               ner_rep_b, emd_rep_b, rel_b2, cr_b2, out);
}